// round 2
// baseline (speedup 1.0000x reference)
#include <cuda_runtime.h>
#include <cuda_bf16.h>
#include <math.h>

// Problem dims (fixed by the reference)
#define BB 16
#define CC 256
#define LL 2048
#define EPS 1e-5f

// ---------------------------------------------------------------------------
// Scratch (no cudaMalloc allowed -> __device__ globals)
// ---------------------------------------------------------------------------
__device__ float d_g    [(size_t)BB * CC * LL];          // 33.5 MB
__device__ float d_theta[(size_t)BB * CC * LL];
__device__ float d_phi  [(size_t)BB * CC * LL];
__device__ float d_f    [(size_t)BB * LL * LL];          // 268 MB (softmax in-place)
__device__ float d_y    [(size_t)BB * CC * LL];
__device__ float d_wy   [(size_t)BB * CC * LL];
__device__ float d_mean [CC];
__device__ float d_rstd [CC];

// ---------------------------------------------------------------------------
// Generic batched SGEMM: C[m,n] = sum_k A(m,k)*B(k,n) (+ bias[m])
//   TA==0: A(m,k)=A[m*lda+k]   TA==1: A(m,k)=A[k*lda+m]
//   TB==0: B(k,n)=B[k*ldb+n]   TB==1: B(k,n)=B[n*ldb+k]
// Tiles: 128x128x16, 256 threads, 8x8 per-thread micro-tile with split-64
// column/row layout for conflict-free float4 smem reads.
// ---------------------------------------------------------------------------
template<int TA, int TB>
__global__ __launch_bounds__(256, 2)
void sgemm_kernel(const float* __restrict__ A, const float* __restrict__ B,
                  const float* __restrict__ bias, float* __restrict__ Cout,
                  int M, int N, int K, int lda, int ldb, int ldc,
                  size_t sA, size_t sB, size_t sC)
{
    constexpr int BM = 128, BN = 128, BK = 16;
    __shared__ float As[BK][BM];
    __shared__ float Bs[BK][BN];

    A    += (size_t)blockIdx.z * sA;
    B    += (size_t)blockIdx.z * sB;
    Cout += (size_t)blockIdx.z * sC;

    const int tid  = threadIdx.x;
    const int tcol = tid & 15;   // 16 cols of threads
    const int trow = tid >> 4;   // 16 rows of threads
    const int mBase = blockIdx.y * BM;
    const int nBase = blockIdx.x * BN;

    float acc[8][8];
#pragma unroll
    for (int i = 0; i < 8; i++)
#pragma unroll
        for (int j = 0; j < 8; j++) acc[i][j] = 0.f;

    for (int k0 = 0; k0 < K; k0 += BK) {
        // ---- load A tile into As[k][m] ----
        if (TA == 0) {
#pragma unroll
            for (int t = tid; t < BM * BK; t += 256) {
                int k = t & (BK - 1), m = t >> 4;
                As[k][m] = A[(size_t)(mBase + m) * lda + (k0 + k)];
            }
        } else {
#pragma unroll
            for (int t = tid; t < BM * BK; t += 256) {
                int m = t & (BM - 1), k = t >> 7;
                As[k][m] = A[(size_t)(k0 + k) * lda + (mBase + m)];
            }
        }
        // ---- load B tile into Bs[k][n] ----
        if (TB == 0) {
#pragma unroll
            for (int t = tid; t < BK * BN; t += 256) {
                int n = t & (BN - 1), k = t >> 7;
                Bs[k][n] = B[(size_t)(k0 + k) * ldb + (nBase + n)];
            }
        } else {
#pragma unroll
            for (int t = tid; t < BK * BN; t += 256) {
                int k = t & (BK - 1), n = t >> 4;
                Bs[k][n] = B[(size_t)(nBase + n) * ldb + (k0 + k)];
            }
        }
        __syncthreads();

#pragma unroll
        for (int k = 0; k < BK; k++) {
            float a[8], b[8];
            *(float4*)&a[0] = *(const float4*)&As[k][trow * 4];
            *(float4*)&a[4] = *(const float4*)&As[k][64 + trow * 4];
            *(float4*)&b[0] = *(const float4*)&Bs[k][tcol * 4];
            *(float4*)&b[4] = *(const float4*)&Bs[k][64 + tcol * 4];
#pragma unroll
            for (int i = 0; i < 8; i++)
#pragma unroll
                for (int j = 0; j < 8; j++)
                    acc[i][j] += a[i] * b[j];
        }
        __syncthreads();
    }

    // ---- epilogue: optional bias, float4 stores ----
#pragma unroll
    for (int i = 0; i < 8; i++) {
        int m = mBase + ((i < 4) ? (trow * 4 + i) : (64 + trow * 4 + i - 4));
        float bv = bias ? bias[m] : 0.f;
        float4 v0, v1;
        v0.x = acc[i][0] + bv; v0.y = acc[i][1] + bv;
        v0.z = acc[i][2] + bv; v0.w = acc[i][3] + bv;
        v1.x = acc[i][4] + bv; v1.y = acc[i][5] + bv;
        v1.z = acc[i][6] + bv; v1.w = acc[i][7] + bv;
        *(float4*)&Cout[(size_t)m * ldc + nBase + tcol * 4]      = v0;
        *(float4*)&Cout[(size_t)m * ldc + nBase + 64 + tcol * 4] = v1;
    }
}

// ---------------------------------------------------------------------------
// Row softmax over rows of length LL (in-place). One block (256 thr) per row.
// ---------------------------------------------------------------------------
__global__ __launch_bounds__(256)
void softmax_kernel(float* __restrict__ f)
{
    __shared__ float red[8];
    float* p = f + (size_t)blockIdx.x * LL;
    const int tid = threadIdx.x;

    float v[8];
    float m = -INFINITY;
#pragma unroll
    for (int j = 0; j < 8; j++) {
        v[j] = p[tid + j * 256];
        m = fmaxf(m, v[j]);
    }
#pragma unroll
    for (int o = 16; o; o >>= 1) m = fmaxf(m, __shfl_xor_sync(0xffffffffu, m, o));
    if ((tid & 31) == 0) red[tid >> 5] = m;
    __syncthreads();
    float bm = red[0];
#pragma unroll
    for (int w = 1; w < 8; w++) bm = fmaxf(bm, red[w]);

    float s = 0.f;
#pragma unroll
    for (int j = 0; j < 8; j++) {
        v[j] = expf(v[j] - bm);
        s += v[j];
    }
#pragma unroll
    for (int o = 16; o; o >>= 1) s += __shfl_xor_sync(0xffffffffu, s, o);
    __syncthreads();
    if ((tid & 31) == 0) red[tid >> 5] = s;
    __syncthreads();
    float bs = 0.f;
#pragma unroll
    for (int w = 0; w < 8; w++) bs += red[w];
    float inv = 1.f / bs;
#pragma unroll
    for (int j = 0; j < 8; j++) p[tid + j * 256] = v[j] * inv;
}

// ---------------------------------------------------------------------------
// BatchNorm batch stats: one block per channel, reduce over (B, L)
// ---------------------------------------------------------------------------
__global__ __launch_bounds__(256)
void bn_stats_kernel(const float* __restrict__ wy,
                     float* __restrict__ mean, float* __restrict__ rstd)
{
    __shared__ float rs[8], rss[8];
    const int c = blockIdx.x;
    float s = 0.f, ss = 0.f;
    for (int t = threadIdx.x; t < BB * LL; t += 256) {
        int b = t >> 11;          // t / LL
        int l = t & (LL - 1);
        float v = wy[(size_t)b * CC * LL + (size_t)c * LL + l];
        s += v; ss += v * v;
    }
#pragma unroll
    for (int o = 16; o; o >>= 1) {
        s  += __shfl_xor_sync(0xffffffffu, s,  o);
        ss += __shfl_xor_sync(0xffffffffu, ss, o);
    }
    if ((threadIdx.x & 31) == 0) { rs[threadIdx.x >> 5] = s; rss[threadIdx.x >> 5] = ss; }
    __syncthreads();
    if (threadIdx.x == 0) {
        float ts = 0.f, tss = 0.f;
#pragma unroll
        for (int w = 0; w < 8; w++) { ts += rs[w]; tss += rss[w]; }
        float inv_n = 1.f / (float)(BB * LL);
        float mu  = ts * inv_n;
        float var = tss * inv_n - mu * mu;
        mean[c] = mu;
        rstd[c] = rsqrtf(var + EPS);
    }
}

// ---------------------------------------------------------------------------
// Final: gamma*(wy-mu)*rstd + beta + x
// ---------------------------------------------------------------------------
__global__ __launch_bounds__(256)
void bn_apply_kernel(const float* __restrict__ wy, const float* __restrict__ x,
                     const float* __restrict__ gamma, const float* __restrict__ beta,
                     const float* __restrict__ mean, const float* __restrict__ rstd,
                     float* __restrict__ out)
{
    size_t i = (size_t)blockIdx.x * 256 + threadIdx.x;
    int c = (int)((i >> 11) & (CC - 1));   // (i / LL) % CC
    out[i] = gamma[c] * (wy[i] - mean[c]) * rstd[c] + beta[c] + x[i];
}

// ---------------------------------------------------------------------------
// Launch
// ---------------------------------------------------------------------------
extern "C" void kernel_launch(void* const* d_in, const int* in_sizes, int n_in,
                              void* d_out, int out_size)
{
    const float* x     = (const float*)d_in[0];
    const float* Wg    = (const float*)d_in[1];
    const float* bg    = (const float*)d_in[2];
    const float* Wt    = (const float*)d_in[3];
    const float* bt    = (const float*)d_in[4];
    const float* Wp    = (const float*)d_in[5];
    const float* bp    = (const float*)d_in[6];
    const float* Ww    = (const float*)d_in[7];
    const float* bw    = (const float*)d_in[8];
    const float* gamma = (const float*)d_in[9];
    const float* beta  = (const float*)d_in[10];
    float* out = (float*)d_out;

    float *g, *theta, *phi, *f, *y, *wy, *mean, *rstd;
    cudaGetSymbolAddress((void**)&g,     d_g);
    cudaGetSymbolAddress((void**)&theta, d_theta);
    cudaGetSymbolAddress((void**)&phi,   d_phi);
    cudaGetSymbolAddress((void**)&f,     d_f);
    cudaGetSymbolAddress((void**)&y,     d_y);
    cudaGetSymbolAddress((void**)&wy,    d_wy);
    cudaGetSymbolAddress((void**)&mean,  d_mean);
    cudaGetSymbolAddress((void**)&rstd,  d_rstd);

    const size_t sX = (size_t)CC * LL;   // per-batch stride for (C,L) tensors
    const size_t sF = (size_t)LL * LL;   // per-batch stride for (L,L)

    // --- Stage 1: pointwise convs g, theta, phi (M=C, N=L, K=C per batch) ---
    {
        dim3 grid(LL / 128, CC / 128, BB);
        sgemm_kernel<0, 0><<<grid, 256>>>(Wg, x, bg, g,     CC, LL, CC, CC, LL, LL, 0, sX, sX);
        sgemm_kernel<0, 0><<<grid, 256>>>(Wt, x, bt, theta, CC, LL, CC, CC, LL, LL, 0, sX, sX);
        sgemm_kernel<0, 0><<<grid, 256>>>(Wp, x, bp, phi,   CC, LL, CC, CC, LL, LL, 0, sX, sX);
    }

    // --- Stage 2: f[l,m] = sum_c theta[c,l] * phi[c,m]  (M=N=L, K=C) ---
    {
        dim3 grid(LL / 128, LL / 128, BB);
        sgemm_kernel<1, 0><<<grid, 256>>>(theta, phi, nullptr, f, LL, LL, CC, LL, LL, LL, sX, sX, sF);
    }

    // --- Stage 3: softmax over last dim of f, in place ---
    softmax_kernel<<<BB * LL, 256>>>(f);

    // --- Stage 4: y[c,l] = sum_m g[c,m] * P[l,m]  (M=C, N=L, K=L) ---
    {
        dim3 grid(LL / 128, CC / 128, BB);
        sgemm_kernel<0, 1><<<grid, 256>>>(g, f, nullptr, y, CC, LL, LL, LL, LL, LL, sX, sF, sX);
    }

    // --- Stage 5: W_y = Ww . y + bw ---
    {
        dim3 grid(LL / 128, CC / 128, BB);
        sgemm_kernel<0, 0><<<grid, 256>>>(Ww, y, bw, wy, CC, LL, CC, CC, LL, LL, 0, sX, sX);
    }

    // --- Stage 6: BN batch stats ---
    bn_stats_kernel<<<CC, 256>>>(wy, mean, rstd);

    // --- Stage 7: normalize + residual ---
    bn_apply_kernel<<<(BB * CC * LL) / 256, 256>>>(wy, x, gamma, beta, mean, rstd, out);
}

// round 4
// speedup vs baseline: 2.7667x; 2.7667x over previous
#include <cuda_runtime.h>
#include <cuda_bf16.h>
#include <math.h>
#include <stdint.h>

#define BB 16
#define CC 256
#define LL 2048
#define EPS 1e-5f

// ======================= helpers =======================
__device__ __forceinline__ uint32_t smem_to_u32(const void* p) {
    uint32_t a;
    asm("{ .reg .u64 t; cvta.to.shared.u64 t, %1; cvt.u32.u64 %0, t; }" : "=r"(a) : "l"(p));
    return a;
}
__device__ __forceinline__ void cp_async16(uint32_t s, const void* g) {
    asm volatile("cp.async.cg.shared.global [%0], [%1], 16;" :: "r"(s), "l"(g));
}
#define CP_COMMIT() asm volatile("cp.async.commit_group;" ::: "memory")
#define CP_WAIT(n)  asm volatile("cp.async.wait_group %0;" :: "n"(n) : "memory")

__device__ __forceinline__ void ldsm4(uint32_t* r, uint32_t a) {
    asm volatile("ldmatrix.sync.aligned.m8n8.x4.shared.b16 {%0,%1,%2,%3}, [%4];"
                 : "=r"(r[0]), "=r"(r[1]), "=r"(r[2]), "=r"(r[3]) : "r"(a));
}
__device__ __forceinline__ void mma16816(float* c, const uint32_t* a, uint32_t b0, uint32_t b1) {
    asm volatile("mma.sync.aligned.m16n8k16.row.col.f32.bf16.bf16.f32 "
                 "{%0,%1,%2,%3}, {%4,%5,%6,%7}, {%8,%9}, {%0,%1,%2,%3};"
                 : "+f"(c[0]), "+f"(c[1]), "+f"(c[2]), "+f"(c[3])
                 : "r"(a[0]), "r"(a[1]), "r"(a[2]), "r"(a[3]), "r"(b0), "r"(b1));
}
__device__ __forceinline__ uint32_t pack_bf16x2(__nv_bfloat16 a, __nv_bfloat16 b) {
    __nv_bfloat162 t = __halves2bfloat162(a, b);
    return *reinterpret_cast<uint32_t*>(&t);
}

// ======================= scratch =======================
#define NLC  ((size_t)BB * LL * CC)
#define NLLs ((size_t)BB * LL * LL)

__device__ __align__(256) __nv_bfloat16 d_xT_hi[NLC], d_xT_lo[NLC];
__device__ __align__(256) __nv_bfloat16 d_w_hi[4 * CC * CC], d_w_lo[4 * CC * CC];
__device__ __align__(256) __nv_bfloat16 d_thT_hi[NLC], d_thT_lo[NLC];
__device__ __align__(256) __nv_bfloat16 d_phT_hi[NLC], d_phT_lo[NLC];
__device__ __align__(256) __nv_bfloat16 d_g_hi[NLC], d_g_lo[NLC];
__device__ __align__(256) float         d_f[NLLs];
__device__ __align__(256) __nv_bfloat16 d_P_hi[NLLs], d_P_lo[NLLs];
__device__ __align__(256) __nv_bfloat16 d_yT_hi[NLC], d_yT_lo[NLC];
__device__ __align__(256) float         d_wyT[NLC];
__device__ float d_psum[128 * CC], d_psq[128 * CC];
__device__ float d_mean[CC], d_rstd[CC];

// ======================= prep kernels =======================
__global__ __launch_bounds__(256)
void split_kernel(const float* __restrict__ src, __nv_bfloat16* __restrict__ hi,
                  __nv_bfloat16* __restrict__ lo, int n)
{
    int i = blockIdx.x * 256 + threadIdx.x;
    if (i < n) {
        float v = src[i];
        __nv_bfloat16 h = __float2bfloat16(v);
        hi[i] = h;
        lo[i] = __float2bfloat16(v - __bfloat162float(h));
    }
}

__global__ __launch_bounds__(256)
void transpose_split_kernel(const float* __restrict__ src,
                            __nv_bfloat16* __restrict__ dhi, __nv_bfloat16* __restrict__ dlo,
                            int R, int S)
{
    __shared__ float tile[32][33];
    const size_t bo = (size_t)R * S * blockIdx.z;
    const int s0 = blockIdx.x * 32, r0 = blockIdx.y * 32;
    const int tx = threadIdx.x, ty = threadIdx.y;
#pragma unroll
    for (int k = 0; k < 4; k++)
        tile[ty + 8 * k][tx] = src[bo + (size_t)(r0 + ty + 8 * k) * S + s0 + tx];
    __syncthreads();
#pragma unroll
    for (int k = 0; k < 4; k++) {
        float v = tile[tx][ty + 8 * k];
        __nv_bfloat16 h = __float2bfloat16(v);
        size_t di = bo + (size_t)(s0 + ty + 8 * k) * R + r0 + tx;
        dhi[di] = h;
        dlo[di] = __float2bfloat16(v - __bfloat162float(h));
    }
}

// ======================= split-bf16 mma.sync GEMM =======================
// D[m,n] = sum_k A(m,k)*B(n,k); A/B K-major bf16 hi/lo; 3 K-passes fp32 acc.
// Tile 128x128x64; 8 warps (2x4), each 64x32 via m16n8k16.
// EPI=0: fp32 out (+bias); EPI=1: split bf16 out (+bias).
// BIASROW=0: bias[n]; BIASROW=1: bias[m].
#define GBM 128
#define GBN 128
#define GBK 64
#define STAGE 32768           // A 16KB + B 16KB
#define NSTAGE 3
#define SM_DYN (NSTAGE * STAGE)

template<int EPI, int BIASROW>
__global__ __launch_bounds__(256, 2)
void gemm_split_kernel(const __nv_bfloat16* __restrict__ Ahi, const __nv_bfloat16* __restrict__ Alo,
                       const __nv_bfloat16* __restrict__ Bhi, const __nv_bfloat16* __restrict__ Blo,
                       const float* __restrict__ bias,
                       float* __restrict__ Cf,
                       __nv_bfloat16* __restrict__ Chi, __nv_bfloat16* __restrict__ Clo,
                       int K, int lda, int ldb, int ldc,
                       size_t sA, size_t sB, size_t sC)
{
    extern __shared__ char smem[];
    const uint32_t sbase = smem_to_u32(smem);

    const int tid  = threadIdx.x;
    const int lane = tid & 31;
    const int wid  = tid >> 5;
    const int wm   = wid >> 2;          // 0..1
    const int wn   = wid & 3;           // 0..3

    const size_t aoff = (size_t)blockIdx.z * sA;
    const size_t boff = (size_t)blockIdx.z * sB;
    const int mBase = blockIdx.y * GBM;
    const int nBase = blockIdx.x * GBN;
    const int KC = K / GBK, NCH = 3 * KC;

    float acc[4][4][4];
#pragma unroll
    for (int i = 0; i < 4; i++)
#pragma unroll
        for (int j = 0; j < 4; j++)
#pragma unroll
            for (int q = 0; q < 4; q++) acc[i][j][q] = 0.f;

    // per-thread load coords (4 A chunks + 4 B chunks of 16B per stage)
    const int lr = tid >> 1;                 // not used; kept simple below

    auto issue_chunk = [&](int ch) {
        const int s = ch % NSTAGE;
        const int pass = ch / KC;
        const int koff = (ch - pass * KC) * GBK;
        const __nv_bfloat16* pa = ((pass < 2) ? Ahi : Alo) + aoff;
        const __nv_bfloat16* pb = ((pass == 1) ? Blo : Bhi) + boff;
        const uint32_t Ab = sbase + s * STAGE;
        const uint32_t Bb = Ab + 16384;
#pragma unroll
        for (int i = 0; i < 4; i++) {
            int idx = tid + i * 256;
            int r = idx >> 3, c = idx & 7;
            uint32_t d = Ab + r * 128 + ((c ^ (r & 7)) << 4);
            cp_async16(d, pa + (size_t)(mBase + r) * lda + koff + c * 8);
        }
#pragma unroll
        for (int i = 0; i < 4; i++) {
            int idx = tid + i * 256;
            int r = idx >> 3, c = idx & 7;
            uint32_t d = Bb + r * 128 + ((c ^ (r & 7)) << 4);
            cp_async16(d, pb + (size_t)(nBase + r) * ldb + koff + c * 8);
        }
    };

    // prologue: stages 0,1
    issue_chunk(0); CP_COMMIT();
    if (NCH > 1) issue_chunk(1);
    CP_COMMIT();

    // per-lane ldmatrix row components
    const int laA = lane & 15;           // A row within 16
    const int lcA = lane >> 4;           // A chunk half (col/8)
    const int lrB = ((lane >> 4) << 3) + (lane & 7);  // B row within 16
    const int lcB = (lane >> 3) & 1;     // B chunk half

    for (int ch = 0; ch < NCH; ch++) {
        __syncthreads();                  // protect stage (ch+2)%3 from prev compute
        if (ch + 2 < NCH) issue_chunk(ch + 2);
        CP_COMMIT();
        CP_WAIT(2);                       // stage ch ready
        __syncthreads();

        const int s = ch % NSTAGE;
        const uint32_t Ab = sbase + s * STAGE;
        const uint32_t Bb = Ab + 16384;

#pragma unroll
        for (int ks = 0; ks < 4; ks++) {
            uint32_t afr[4][4];
#pragma unroll
            for (int i = 0; i < 4; i++) {
                int row = wm * 64 + i * 16 + laA;
                int chk = ks * 2 + lcA;
                ldsm4(afr[i], Ab + row * 128 + ((chk ^ (row & 7)) << 4));
            }
            uint32_t bfr[2][4];
#pragma unroll
            for (int j = 0; j < 2; j++) {
                int row = wn * 32 + j * 16 + lrB;
                int chk = ks * 2 + lcB;
                ldsm4(bfr[j], Bb + row * 128 + ((chk ^ (row & 7)) << 4));
            }
#pragma unroll
            for (int i = 0; i < 4; i++)
#pragma unroll
                for (int j = 0; j < 4; j++)
                    mma16816(acc[i][j], afr[i], bfr[j >> 1][(j & 1) * 2],
                             bfr[j >> 1][(j & 1) * 2 + 1]);
        }
    }

    // ---- epilogue ----
    const int g  = lane >> 2;
    const int tg = lane & 3;
#pragma unroll
    for (int i = 0; i < 4; i++) {
        const int rm0 = mBase + wm * 64 + i * 16 + g;
        const int rm1 = rm0 + 8;
        float rb0 = 0.f, rb1 = 0.f;
        if (BIASROW && bias) { rb0 = bias[rm0]; rb1 = bias[rm1]; }
#pragma unroll
        for (int j = 0; j < 4; j++) {
            const int cn = nBase + wn * 32 + j * 8 + tg * 2;
            float c0 = acc[i][j][0], c1 = acc[i][j][1];
            float c2 = acc[i][j][2], c3 = acc[i][j][3];
            if (bias) {
                if (BIASROW) { c0 += rb0; c1 += rb0; c2 += rb1; c3 += rb1; }
                else {
                    float b0 = bias[cn], b1 = bias[cn + 1];
                    c0 += b0; c1 += b1; c2 += b0; c3 += b1;
                }
            }
            const size_t o0 = (size_t)blockIdx.z * sC + (size_t)rm0 * ldc + cn;
            const size_t o1 = (size_t)blockIdx.z * sC + (size_t)rm1 * ldc + cn;
            if (EPI == 0) {
                *(float2*)(Cf + o0) = make_float2(c0, c1);
                *(float2*)(Cf + o1) = make_float2(c2, c3);
            } else {
                __nv_bfloat16 h0 = __float2bfloat16(c0), h1 = __float2bfloat16(c1);
                __nv_bfloat16 h2 = __float2bfloat16(c2), h3 = __float2bfloat16(c3);
                __nv_bfloat16 l0 = __float2bfloat16(c0 - __bfloat162float(h0));
                __nv_bfloat16 l1 = __float2bfloat16(c1 - __bfloat162float(h1));
                __nv_bfloat16 l2 = __float2bfloat16(c2 - __bfloat162float(h2));
                __nv_bfloat16 l3 = __float2bfloat16(c3 - __bfloat162float(h3));
                *(uint32_t*)(Chi + o0) = pack_bf16x2(h0, h1);
                *(uint32_t*)(Chi + o1) = pack_bf16x2(h2, h3);
                *(uint32_t*)(Clo + o0) = pack_bf16x2(l0, l1);
                *(uint32_t*)(Clo + o1) = pack_bf16x2(l2, l3);
            }
        }
    }
}

// ======================= softmax (fp32 in -> split bf16 out) =======================
__global__ __launch_bounds__(256)
void softmax_split_kernel(const float* __restrict__ f,
                          __nv_bfloat16* __restrict__ phi, __nv_bfloat16* __restrict__ plo)
{
    __shared__ float red[8];
    const size_t ro = (size_t)blockIdx.x * LL;
    const int tid = threadIdx.x;
    float v[8];
    float m = -INFINITY;
#pragma unroll
    for (int j = 0; j < 8; j++) {
        v[j] = f[ro + tid + j * 256];
        m = fmaxf(m, v[j]);
    }
#pragma unroll
    for (int o = 16; o; o >>= 1) m = fmaxf(m, __shfl_xor_sync(0xffffffffu, m, o));
    if ((tid & 31) == 0) red[tid >> 5] = m;
    __syncthreads();
    float bm = red[0];
#pragma unroll
    for (int w = 1; w < 8; w++) bm = fmaxf(bm, red[w]);
    float s = 0.f;
#pragma unroll
    for (int j = 0; j < 8; j++) { v[j] = __expf(v[j] - bm); s += v[j]; }
#pragma unroll
    for (int o = 16; o; o >>= 1) s += __shfl_xor_sync(0xffffffffu, s, o);
    __syncthreads();
    if ((tid & 31) == 0) red[tid >> 5] = s;
    __syncthreads();
    float bs = 0.f;
#pragma unroll
    for (int w = 0; w < 8; w++) bs += red[w];
    const float inv = 1.f / bs;
#pragma unroll
    for (int j = 0; j < 8; j++) {
        float p = v[j] * inv;
        __nv_bfloat16 h = __float2bfloat16(p);
        phi[ro + tid + j * 256] = h;
        plo[ro + tid + j * 256] = __float2bfloat16(p - __bfloat162float(h));
    }
}

// ======================= BatchNorm =======================
__global__ __launch_bounds__(256)
void bn_partial_kernel(const float* __restrict__ wyT, float* __restrict__ psum, float* __restrict__ psq)
{
    const int c = threadIdx.x;
    float s = 0.f, q = 0.f;
    const size_t r0 = (size_t)blockIdx.x * 256;
    for (int r = 0; r < 256; r++) {
        float v = wyT[(r0 + r) * CC + c];
        s += v; q += v * v;
    }
    psum[blockIdx.x * CC + c] = s;
    psq [blockIdx.x * CC + c] = q;
}

__global__ __launch_bounds__(256)
void bn_final_kernel(const float* __restrict__ psum, const float* __restrict__ psq,
                     float* __restrict__ mean, float* __restrict__ rstd)
{
    const int c = threadIdx.x;
    float s = 0.f, q = 0.f;
    for (int i = 0; i < 128; i++) { s += psum[i * CC + c]; q += psq[i * CC + c]; }
    const float inv_n = 1.f / (float)(BB * LL);
    float mu = s * inv_n;
    mean[c] = mu;
    rstd[c] = rsqrtf(q * inv_n - mu * mu + EPS);
}

__global__ __launch_bounds__(256)
void bn_apply_kernel(const float* __restrict__ wyT, const float* __restrict__ x,
                     const float* __restrict__ gamma, const float* __restrict__ beta,
                     const float* __restrict__ mean, const float* __restrict__ rstd,
                     float* __restrict__ out)
{
    __shared__ float tile[32][33];
    const int l0 = blockIdx.x * 32, c0 = blockIdx.y * 32;
    const size_t bo = (size_t)blockIdx.z * CC * LL;
    const int tx = threadIdx.x, ty = threadIdx.y;
#pragma unroll
    for (int k = 0; k < 4; k++)
        tile[ty + 8 * k][tx] = wyT[bo + (size_t)(l0 + ty + 8 * k) * CC + c0 + tx];
    __syncthreads();
#pragma unroll
    for (int k = 0; k < 4; k++) {
        const int c = c0 + ty + 8 * k, l = l0 + tx;
        float v = tile[tx][ty + 8 * k];
        size_t oi = bo + (size_t)c * LL + l;
        out[oi] = gamma[c] * (v - mean[c]) * rstd[c] + beta[c] + x[oi];
    }
}

// ======================= launch =======================
extern "C" void kernel_launch(void* const* d_in, const int* in_sizes, int n_in,
                              void* d_out, int out_size)
{
    const float* x     = (const float*)d_in[0];
    const float* Wg    = (const float*)d_in[1];
    const float* bg    = (const float*)d_in[2];
    const float* Wt    = (const float*)d_in[3];
    const float* bt    = (const float*)d_in[4];
    const float* Wp    = (const float*)d_in[5];
    const float* bp    = (const float*)d_in[6];
    const float* Ww    = (const float*)d_in[7];
    const float* bw    = (const float*)d_in[8];
    const float* gamma = (const float*)d_in[9];
    const float* beta  = (const float*)d_in[10];
    float* out = (float*)d_out;

    __nv_bfloat16 *xT_hi, *xT_lo, *w_hi, *w_lo, *thT_hi, *thT_lo, *phT_hi, *phT_lo;
    __nv_bfloat16 *g_hi, *g_lo, *P_hi, *P_lo, *yT_hi, *yT_lo;
    float *f, *wyT, *psum, *psq, *mean, *rstd;
    cudaGetSymbolAddress((void**)&xT_hi, d_xT_hi);
    cudaGetSymbolAddress((void**)&xT_lo, d_xT_lo);
    cudaGetSymbolAddress((void**)&w_hi,  d_w_hi);
    cudaGetSymbolAddress((void**)&w_lo,  d_w_lo);
    cudaGetSymbolAddress((void**)&thT_hi, d_thT_hi);
    cudaGetSymbolAddress((void**)&thT_lo, d_thT_lo);
    cudaGetSymbolAddress((void**)&phT_hi, d_phT_hi);
    cudaGetSymbolAddress((void**)&phT_lo, d_phT_lo);
    cudaGetSymbolAddress((void**)&g_hi,  d_g_hi);
    cudaGetSymbolAddress((void**)&g_lo,  d_g_lo);
    cudaGetSymbolAddress((void**)&f,     d_f);
    cudaGetSymbolAddress((void**)&P_hi,  d_P_hi);
    cudaGetSymbolAddress((void**)&P_lo,  d_P_lo);
    cudaGetSymbolAddress((void**)&yT_hi, d_yT_hi);
    cudaGetSymbolAddress((void**)&yT_lo, d_yT_lo);
    cudaGetSymbolAddress((void**)&wyT,   d_wyT);
    cudaGetSymbolAddress((void**)&psum,  d_psum);
    cudaGetSymbolAddress((void**)&psq,   d_psq);
    cudaGetSymbolAddress((void**)&mean,  d_mean);
    cudaGetSymbolAddress((void**)&rstd,  d_rstd);

    cudaFuncSetAttribute(gemm_split_kernel<0, 0>, cudaFuncAttributeMaxDynamicSharedMemorySize, SM_DYN);
    cudaFuncSetAttribute(gemm_split_kernel<1, 0>, cudaFuncAttributeMaxDynamicSharedMemorySize, SM_DYN);
    cudaFuncSetAttribute(gemm_split_kernel<1, 1>, cudaFuncAttributeMaxDynamicSharedMemorySize, SM_DYN);

    const size_t sLC = (size_t)LL * CC;
    const size_t sLL = (size_t)LL * LL;
    const int WW = CC * CC;

    // ---- prep ----
    {
        dim3 g1(LL / 32, CC / 32, BB), b1(32, 8);
        transpose_split_kernel<<<g1, b1>>>(x, xT_hi, xT_lo, CC, LL);
        split_kernel<<<WW / 256, 256>>>(Wg, w_hi + 0 * WW, w_lo + 0 * WW, WW);
        split_kernel<<<WW / 256, 256>>>(Wt, w_hi + 1 * WW, w_lo + 1 * WW, WW);
        split_kernel<<<WW / 256, 256>>>(Wp, w_hi + 2 * WW, w_lo + 2 * WW, WW);
        split_kernel<<<WW / 256, 256>>>(Ww, w_hi + 3 * WW, w_lo + 3 * WW, WW);
    }

    // ---- stage 1: thetaT, phiT (B,L,C); g (B,C,L) ----
    {
        dim3 grid(CC / GBN, LL / GBM, BB);
        gemm_split_kernel<1, 0><<<grid, 256, SM_DYN>>>(
            xT_hi, xT_lo, w_hi + 1 * WW, w_lo + 1 * WW, bt,
            nullptr, thT_hi, thT_lo, CC, CC, CC, CC, sLC, 0, sLC);
        gemm_split_kernel<1, 0><<<grid, 256, SM_DYN>>>(
            xT_hi, xT_lo, w_hi + 2 * WW, w_lo + 2 * WW, bp,
            nullptr, phT_hi, phT_lo, CC, CC, CC, CC, sLC, 0, sLC);
        dim3 gridg(LL / GBN, CC / GBM, BB);
        gemm_split_kernel<1, 1><<<gridg, 256, SM_DYN>>>(
            w_hi + 0 * WW, w_lo + 0 * WW, xT_hi, xT_lo, bg,
            nullptr, g_hi, g_lo, CC, CC, CC, LL, 0, sLC, sLC);
    }

    // ---- stage 2: f = thetaT . phiT^T ----
    {
        dim3 grid(LL / GBN, LL / GBM, BB);
        gemm_split_kernel<0, 0><<<grid, 256, SM_DYN>>>(
            thT_hi, thT_lo, phT_hi, phT_lo, nullptr,
            f, nullptr, nullptr, CC, CC, CC, LL, sLC, sLC, sLL);
    }

    // ---- stage 3: softmax rows -> split P ----
    softmax_split_kernel<<<BB * LL, 256>>>(f, P_hi, P_lo);

    // ---- stage 4: yT[l,c] = sum_m P[l,m] g[c,m] ----
    {
        dim3 grid(CC / GBN, LL / GBM, BB);
        gemm_split_kernel<1, 0><<<grid, 256, SM_DYN>>>(
            P_hi, P_lo, g_hi, g_lo, nullptr,
            nullptr, yT_hi, yT_lo, LL, LL, LL, CC, sLL, sLC, sLC);
    }

    // ---- stage 5: wyT = yT . Ww^T + bw ----
    {
        dim3 grid(CC / GBN, LL / GBM, BB);
        gemm_split_kernel<0, 0><<<grid, 256, SM_DYN>>>(
            yT_hi, yT_lo, w_hi + 3 * WW, w_lo + 3 * WW, bw,
            wyT, nullptr, nullptr, CC, CC, CC, CC, sLC, 0, sLC);
    }

    // ---- BN ----
    bn_partial_kernel<<<128, 256>>>(wyT, psum, psq);
    bn_final_kernel<<<1, 256>>>(psum, psq, mean, rstd);
    {
        dim3 g2(LL / 32, CC / 32, BB), b2(32, 8);
        bn_apply_kernel<<<g2, b2>>>(wyT, x, gamma, beta, mean, rstd, out);
    }
}

// round 6
// speedup vs baseline: 3.5167x; 1.2711x over previous
#include <cuda_runtime.h>
#include <cuda_fp16.h>
#include <math.h>
#include <stdint.h>

#define BB 16
#define CC 256
#define LL 2048
#define EPS 1e-5f

// ======================= helpers =======================
__device__ __forceinline__ uint32_t smem_to_u32(const void* p) {
    uint32_t a;
    asm("{ .reg .u64 t; cvta.to.shared.u64 t, %1; cvt.u32.u64 %0, t; }" : "=r"(a) : "l"(p));
    return a;
}
__device__ __forceinline__ void cp_async16(uint32_t s, const void* g) {
    asm volatile("cp.async.cg.shared.global [%0], [%1], 16;" :: "r"(s), "l"(g));
}
#define CP_COMMIT() asm volatile("cp.async.commit_group;" ::: "memory")
#define CP_WAIT(n)  asm volatile("cp.async.wait_group %0;" :: "n"(n) : "memory")

__device__ __forceinline__ void ldsm4(uint32_t* r, uint32_t a) {
    asm volatile("ldmatrix.sync.aligned.m8n8.x4.shared.b16 {%0,%1,%2,%3}, [%4];"
                 : "=r"(r[0]), "=r"(r[1]), "=r"(r[2]), "=r"(r[3]) : "r"(a));
}
__device__ __forceinline__ void mma16816(float* c, const uint32_t* a, uint32_t b0, uint32_t b1) {
    asm volatile("mma.sync.aligned.m16n8k16.row.col.f32.f16.f16.f32 "
                 "{%0,%1,%2,%3}, {%4,%5,%6,%7}, {%8,%9}, {%0,%1,%2,%3};"
                 : "+f"(c[0]), "+f"(c[1]), "+f"(c[2]), "+f"(c[3])
                 : "r"(a[0]), "r"(a[1]), "r"(a[2]), "r"(a[3]), "r"(b0), "r"(b1));
}
__device__ __forceinline__ uint32_t pack_h2(__half a, __half b) {
    __half2 t = __halves2half2(a, b);
    return *reinterpret_cast<uint32_t*>(&t);
}

// ======================= scratch =======================
#define NLC  ((size_t)BB * LL * CC)
#define NLLs ((size_t)BB * LL * LL)

__device__ __align__(256) __half d_xT_hi[NLC], d_xT_lo[NLC];       // x^T (B,L,C)
__device__ __align__(256) __half d_Mt_hi[CC * CC], d_Mt_lo[CC * CC]; // Wp^T Wt
__device__ __align__(256) __half d_Nt_hi[CC * CC], d_Nt_lo[CC * CC]; // Ww Wg
__device__ float d_qv[CC], d_rv[CC];                                // Wp^T bt ; Ww bg
__device__ __align__(256) __half d_kT_hi[NLC], d_kT_lo[NLC];       // kappa^T (B,L,C)
__device__ __align__(256) __half d_e_hi[NLC], d_e_lo[NLC];         // eta (B,C,L)
__device__ __align__(256) float  d_f[NLLs];                        // logits (B,L,L)
__device__ __align__(256) __half d_P[NLLs];                        // softmax fp16
__device__ __align__(256) float  d_wyT[NLC];                       // W_y^T (B,L,C)
__device__ float d_psum[128 * CC], d_psq[128 * CC];
__device__ float d_mean[CC], d_rstd[CC];

// ======================= prep kernels =======================
// transpose + fp16 split: x (B,C,L) -> xT (B,L,C) hi/lo
__global__ __launch_bounds__(256)
void transpose_split_kernel(const float* __restrict__ src,
                            __half* __restrict__ dhi, __half* __restrict__ dlo,
                            int R, int S)
{
    __shared__ float tile[32][33];
    const size_t bo = (size_t)R * S * blockIdx.z;
    const int s0 = blockIdx.x * 32, r0 = blockIdx.y * 32;
    const int tx = threadIdx.x, ty = threadIdx.y;
#pragma unroll
    for (int k = 0; k < 4; k++)
        tile[ty + 8 * k][tx] = src[bo + (size_t)(r0 + ty + 8 * k) * S + s0 + tx];
    __syncthreads();
#pragma unroll
    for (int k = 0; k < 4; k++) {
        float v = tile[tx][ty + 8 * k];
        __half h = __float2half(v);
        size_t di = bo + (size_t)(s0 + ty + 8 * k) * R + r0 + tx;
        dhi[di] = h;
        dlo[di] = __float2half(v - __half2float(h));
    }
}

// Weight products: blockIdx.y==0 -> Mt = Wp^T Wt, qv = Wp^T bt
//                  blockIdx.y==1 -> Nt = Ww Wg,   rv = Ww bg
__global__ __launch_bounds__(256)
void wprep_kernel(const float* __restrict__ Wt, const float* __restrict__ bt,
                  const float* __restrict__ Wp,
                  const float* __restrict__ Wg, const float* __restrict__ bg,
                  const float* __restrict__ Ww,
                  __half* __restrict__ Mhi, __half* __restrict__ Mlo, float* __restrict__ qv,
                  __half* __restrict__ Nhi, __half* __restrict__ Nlo, float* __restrict__ rv)
{
    const int c = blockIdx.x, k = threadIdx.x;
    if (blockIdx.y == 0) {
        float acc = 0.f;
        for (int j = 0; j < CC; j++) acc += Wp[j * CC + c] * Wt[j * CC + k];
        __half h = __float2half(acc);
        Mhi[c * CC + k] = h;
        Mlo[c * CC + k] = __float2half(acc - __half2float(h));
        if (k == 0) {
            float q = 0.f;
            for (int j = 0; j < CC; j++) q += Wp[j * CC + c] * bt[j];
            qv[c] = q;
        }
    } else {
        float acc = 0.f;
        for (int j = 0; j < CC; j++) acc += Ww[c * CC + j] * Wg[j * CC + k];
        __half h = __float2half(acc);
        Nhi[c * CC + k] = h;
        Nlo[c * CC + k] = __float2half(acc - __half2float(h));
        if (k == 0) {
            float r = 0.f;
            for (int j = 0; j < CC; j++) r += Ww[c * CC + j] * bg[j];
            rv[c] = r;
        }
    }
}

// ======================= split-fp16 mma.sync GEMM =======================
// D[m,n] = sum_k A(m,k)*B(n,k); K-major fp16 hi/lo; NPASS fp32-acc passes:
//   pass0 Ahi*Bhi, pass1 Ahi*Blo, pass2 Alo*Bhi  (NPASS=2 skips pass2)
// Tile 128x128x64; 8 warps (2x4), m16n8k16.
// EPI=0: fp32 out (+bias); EPI=1: split fp16 out (+bias).
// BIASROW=0: bias[n]; BIASROW=1: bias[m].
#define GBM 128
#define GBN 128
#define GBK 64
#define STAGE 32768
#define NSTAGE 3
#define SM_DYN (NSTAGE * STAGE)

template<int NPASS, int EPI, int BIASROW>
__global__ __launch_bounds__(256, 2)
void gemm_split_kernel(const __half* __restrict__ Ahi, const __half* __restrict__ Alo,
                       const __half* __restrict__ Bhi, const __half* __restrict__ Blo,
                       const float* __restrict__ bias,
                       float* __restrict__ Cf,
                       __half* __restrict__ Chi, __half* __restrict__ Clo,
                       int K, int lda, int ldb, int ldc,
                       size_t sA, size_t sB, size_t sC)
{
    extern __shared__ char smem[];
    const uint32_t sbase = smem_to_u32(smem);

    const int tid  = threadIdx.x;
    const int lane = tid & 31;
    const int wid  = tid >> 5;
    const int wm   = wid >> 2;
    const int wn   = wid & 3;

    const size_t aoff = (size_t)blockIdx.z * sA;
    const size_t boff = (size_t)blockIdx.z * sB;
    const int mBase = blockIdx.y * GBM;
    const int nBase = blockIdx.x * GBN;
    const int KC = K / GBK, NCH = NPASS * KC;

    float acc[4][4][4];
#pragma unroll
    for (int i = 0; i < 4; i++)
#pragma unroll
        for (int j = 0; j < 4; j++)
#pragma unroll
            for (int q = 0; q < 4; q++) acc[i][j][q] = 0.f;

    auto issue_chunk = [&](int ch) {
        const int s = ch % NSTAGE;
        const int pass = ch / KC;
        const int koff = (ch - pass * KC) * GBK;
        const __half* pa = ((pass < 2) ? Ahi : Alo) + aoff;
        const __half* pb = ((pass == 1) ? Blo : Bhi) + boff;
        const uint32_t Ab = sbase + s * STAGE;
        const uint32_t Bb = Ab + 16384;
#pragma unroll
        for (int i = 0; i < 4; i++) {
            int idx = tid + i * 256;
            int r = idx >> 3, c = idx & 7;
            uint32_t d = Ab + r * 128 + ((c ^ (r & 7)) << 4);
            cp_async16(d, pa + (size_t)(mBase + r) * lda + koff + c * 8);
        }
#pragma unroll
        for (int i = 0; i < 4; i++) {
            int idx = tid + i * 256;
            int r = idx >> 3, c = idx & 7;
            uint32_t d = Bb + r * 128 + ((c ^ (r & 7)) << 4);
            cp_async16(d, pb + (size_t)(nBase + r) * ldb + koff + c * 8);
        }
    };

    issue_chunk(0); CP_COMMIT();
    if (NCH > 1) issue_chunk(1);
    CP_COMMIT();

    const int laA = lane & 15;
    const int lcA = lane >> 4;
    const int lrB = ((lane >> 4) << 3) + (lane & 7);
    const int lcB = (lane >> 3) & 1;

    for (int ch = 0; ch < NCH; ch++) {
        __syncthreads();
        if (ch + 2 < NCH) issue_chunk(ch + 2);
        CP_COMMIT();
        CP_WAIT(2);
        __syncthreads();

        const int s = ch % NSTAGE;
        const uint32_t Ab = sbase + s * STAGE;
        const uint32_t Bb = Ab + 16384;

#pragma unroll
        for (int ks = 0; ks < 4; ks++) {
            uint32_t afr[4][4];
#pragma unroll
            for (int i = 0; i < 4; i++) {
                int row = wm * 64 + i * 16 + laA;
                int chk = ks * 2 + lcA;
                ldsm4(afr[i], Ab + row * 128 + ((chk ^ (row & 7)) << 4));
            }
            uint32_t bfr[2][4];
#pragma unroll
            for (int j = 0; j < 2; j++) {
                int row = wn * 32 + j * 16 + lrB;
                int chk = ks * 2 + lcB;
                ldsm4(bfr[j], Bb + row * 128 + ((chk ^ (row & 7)) << 4));
            }
#pragma unroll
            for (int i = 0; i < 4; i++)
#pragma unroll
                for (int j = 0; j < 4; j++)
                    mma16816(acc[i][j], afr[i], bfr[j >> 1][(j & 1) * 2],
                             bfr[j >> 1][(j & 1) * 2 + 1]);
        }
    }

    // ---- epilogue ----
    const int g  = lane >> 2;
    const int tg = lane & 3;
#pragma unroll
    for (int i = 0; i < 4; i++) {
        const int rm0 = mBase + wm * 64 + i * 16 + g;
        const int rm1 = rm0 + 8;
        float rb0 = 0.f, rb1 = 0.f;
        if (BIASROW && bias) { rb0 = bias[rm0]; rb1 = bias[rm1]; }
#pragma unroll
        for (int j = 0; j < 4; j++) {
            const int cn = nBase + wn * 32 + j * 8 + tg * 2;
            float c0 = acc[i][j][0], c1 = acc[i][j][1];
            float c2 = acc[i][j][2], c3 = acc[i][j][3];
            if (bias) {
                if (BIASROW) { c0 += rb0; c1 += rb0; c2 += rb1; c3 += rb1; }
                else {
                    float b0 = bias[cn], b1 = bias[cn + 1];
                    c0 += b0; c1 += b1; c2 += b0; c3 += b1;
                }
            }
            const size_t o0 = (size_t)blockIdx.z * sC + (size_t)rm0 * ldc + cn;
            const size_t o1 = (size_t)blockIdx.z * sC + (size_t)rm1 * ldc + cn;
            if (EPI == 0) {
                *(float2*)(Cf + o0) = make_float2(c0, c1);
                *(float2*)(Cf + o1) = make_float2(c2, c3);
            } else {
                __half h0 = __float2half(c0), h1 = __float2half(c1);
                __half h2 = __float2half(c2), h3 = __float2half(c3);
                __half l0 = __float2half(c0 - __half2float(h0));
                __half l1 = __float2half(c1 - __half2float(h1));
                __half l2 = __float2half(c2 - __half2float(h2));
                __half l3 = __float2half(c3 - __half2float(h3));
                *(uint32_t*)(Chi + o0) = pack_h2(h0, h1);
                *(uint32_t*)(Chi + o1) = pack_h2(h2, h3);
                *(uint32_t*)(Clo + o0) = pack_h2(l0, l1);
                *(uint32_t*)(Clo + o1) = pack_h2(l2, l3);
            }
        }
    }
}

// ======================= softmax: fp32 logits -> fp16 P =======================
__global__ __launch_bounds__(256)
void softmax_kernel(const float* __restrict__ f, __half* __restrict__ P)
{
    __shared__ float red[8];
    const size_t ro = (size_t)blockIdx.x * LL;
    const int tid = threadIdx.x;
    float v[8];
    float m = -INFINITY;
#pragma unroll
    for (int j = 0; j < 8; j++) {
        v[j] = f[ro + tid + j * 256];
        m = fmaxf(m, v[j]);
    }
#pragma unroll
    for (int o = 16; o; o >>= 1) m = fmaxf(m, __shfl_xor_sync(0xffffffffu, m, o));
    if ((tid & 31) == 0) red[tid >> 5] = m;
    __syncthreads();
    float bm = red[0];
#pragma unroll
    for (int w = 1; w < 8; w++) bm = fmaxf(bm, red[w]);
    float s = 0.f;
#pragma unroll
    for (int j = 0; j < 8; j++) { v[j] = __expf(v[j] - bm); s += v[j]; }
#pragma unroll
    for (int o = 16; o; o >>= 1) s += __shfl_xor_sync(0xffffffffu, s, o);
    __syncthreads();
    if ((tid & 31) == 0) red[tid >> 5] = s;
    __syncthreads();
    float bs = 0.f;
#pragma unroll
    for (int w = 0; w < 8; w++) bs += red[w];
    const float inv = 1.f / bs;
#pragma unroll
    for (int j = 0; j < 8; j++)
        P[ro + tid + j * 256] = __float2half(v[j] * inv);
}

// ======================= BatchNorm =======================
__global__ __launch_bounds__(256)
void bn_partial_kernel(const float* __restrict__ wyT, float* __restrict__ psum, float* __restrict__ psq)
{
    const int c = threadIdx.x;
    float s = 0.f, q = 0.f;
    const size_t r0 = (size_t)blockIdx.x * 256;
    for (int r = 0; r < 256; r++) {
        float v = wyT[(r0 + r) * CC + c];
        s += v; q += v * v;
    }
    psum[blockIdx.x * CC + c] = s;
    psq [blockIdx.x * CC + c] = q;
}

__global__ __launch_bounds__(256)
void bn_final_kernel(const float* __restrict__ psum, const float* __restrict__ psq,
                     float* __restrict__ mean, float* __restrict__ rstd)
{
    const int c = threadIdx.x;
    float s = 0.f, q = 0.f;
    for (int i = 0; i < 128; i++) { s += psum[i * CC + c]; q += psq[i * CC + c]; }
    const float inv_n = 1.f / (float)(BB * LL);
    float mu = s * inv_n;
    mean[c] = mu;
    rstd[c] = rsqrtf(q * inv_n - mu * mu + EPS);
}

__global__ __launch_bounds__(256)
void bn_apply_kernel(const float* __restrict__ wyT, const float* __restrict__ x,
                     const float* __restrict__ gamma, const float* __restrict__ beta,
                     const float* __restrict__ mean, const float* __restrict__ rstd,
                     float* __restrict__ out)
{
    __shared__ float tile[32][33];
    const int l0 = blockIdx.x * 32, c0 = blockIdx.y * 32;
    const size_t bo = (size_t)blockIdx.z * CC * LL;
    const int tx = threadIdx.x, ty = threadIdx.y;
#pragma unroll
    for (int k = 0; k < 4; k++)
        tile[ty + 8 * k][tx] = wyT[bo + (size_t)(l0 + ty + 8 * k) * CC + c0 + tx];
    __syncthreads();
#pragma unroll
    for (int k = 0; k < 4; k++) {
        const int c = c0 + ty + 8 * k, l = l0 + tx;
        float v = tile[tx][ty + 8 * k];
        size_t oi = bo + (size_t)c * LL + l;
        out[oi] = gamma[c] * (v - mean[c]) * rstd[c] + beta[c] + x[oi];
    }
}

// ======================= launch =======================
extern "C" void kernel_launch(void* const* d_in, const int* in_sizes, int n_in,
                              void* d_out, int out_size)
{
    const float* x     = (const float*)d_in[0];
    const float* Wg    = (const float*)d_in[1];
    const float* bg    = (const float*)d_in[2];
    const float* Wt    = (const float*)d_in[3];
    const float* bt    = (const float*)d_in[4];
    const float* Wp    = (const float*)d_in[5];
    const float* bp    = (const float*)d_in[6];   // unused: row-constant under softmax
    const float* Ww    = (const float*)d_in[7];
    const float* bw    = (const float*)d_in[8];
    const float* gamma = (const float*)d_in[9];
    const float* beta  = (const float*)d_in[10];
    float* out = (float*)d_out;
    (void)bp;

    __half *xT_hi, *xT_lo, *Mt_hi, *Mt_lo, *Nt_hi, *Nt_lo, *kT_hi, *kT_lo, *e_hi, *e_lo, *P;
    float *qv, *rv, *f, *wyT, *psum, *psq, *mean, *rstd;
    cudaGetSymbolAddress((void**)&xT_hi, d_xT_hi);
    cudaGetSymbolAddress((void**)&xT_lo, d_xT_lo);
    cudaGetSymbolAddress((void**)&Mt_hi, d_Mt_hi);
    cudaGetSymbolAddress((void**)&Mt_lo, d_Mt_lo);
    cudaGetSymbolAddress((void**)&Nt_hi, d_Nt_hi);
    cudaGetSymbolAddress((void**)&Nt_lo, d_Nt_lo);
    cudaGetSymbolAddress((void**)&qv,    d_qv);
    cudaGetSymbolAddress((void**)&rv,    d_rv);
    cudaGetSymbolAddress((void**)&kT_hi, d_kT_hi);
    cudaGetSymbolAddress((void**)&kT_lo, d_kT_lo);
    cudaGetSymbolAddress((void**)&e_hi,  d_e_hi);
    cudaGetSymbolAddress((void**)&e_lo,  d_e_lo);
    cudaGetSymbolAddress((void**)&f,     d_f);
    cudaGetSymbolAddress((void**)&P,     d_P);
    cudaGetSymbolAddress((void**)&wyT,   d_wyT);
    cudaGetSymbolAddress((void**)&psum,  d_psum);
    cudaGetSymbolAddress((void**)&psq,   d_psq);
    cudaGetSymbolAddress((void**)&mean,  d_mean);
    cudaGetSymbolAddress((void**)&rstd,  d_rstd);

    cudaFuncSetAttribute(gemm_split_kernel<3, 0, 0>, cudaFuncAttributeMaxDynamicSharedMemorySize, SM_DYN);
    cudaFuncSetAttribute(gemm_split_kernel<3, 1, 0>, cudaFuncAttributeMaxDynamicSharedMemorySize, SM_DYN);
    cudaFuncSetAttribute(gemm_split_kernel<3, 1, 1>, cudaFuncAttributeMaxDynamicSharedMemorySize, SM_DYN);
    cudaFuncSetAttribute(gemm_split_kernel<2, 0, 0>, cudaFuncAttributeMaxDynamicSharedMemorySize, SM_DYN);

    const size_t sLC = (size_t)LL * CC;
    const size_t sLL = (size_t)LL * LL;

    // ---- prep: xT split; folded weight products ----
    {
        dim3 g1(LL / 32, CC / 32, BB), b1(32, 8);
        transpose_split_kernel<<<g1, b1>>>(x, xT_hi, xT_lo, CC, LL);
        dim3 gw(CC, 2);
        wprep_kernel<<<gw, CC>>>(Wt, bt, Wp, Wg, bg, Ww,
                                 Mt_hi, Mt_lo, qv, Nt_hi, Nt_lo, rv);
    }

    // ---- G1: kappaT[l,c] = sum_k xT[l,k] Mt[c,k] + qv[c]   (B,L,C) ----
    {
        dim3 grid(CC / GBN, LL / GBM, BB);
        gemm_split_kernel<3, 1, 0><<<grid, 256, SM_DYN>>>(
            xT_hi, xT_lo, Mt_hi, Mt_lo, qv,
            nullptr, kT_hi, kT_lo, CC, CC, CC, CC, sLC, 0, sLC);
    }
    // ---- G2: eta[c,l] = sum_k Nt[c,k] xT[l,k] + rv[c]   (B,C,L) ----
    {
        dim3 grid(LL / GBN, CC / GBM, BB);
        gemm_split_kernel<3, 1, 1><<<grid, 256, SM_DYN>>>(
            Nt_hi, Nt_lo, xT_hi, xT_lo, rv,
            nullptr, e_hi, e_lo, CC, CC, CC, LL, 0, sLC, sLC);
    }
    // ---- G3: f[l,m] = sum_c kappaT[l,c] xT[m,c]  (logits up to row-const) ----
    {
        dim3 grid(LL / GBN, LL / GBM, BB);
        gemm_split_kernel<3, 0, 0><<<grid, 256, SM_DYN>>>(
            kT_hi, kT_lo, xT_hi, xT_lo, nullptr,
            f, nullptr, nullptr, CC, CC, CC, LL, sLC, sLC, sLL);
    }
    // ---- softmax -> P fp16 ----
    softmax_kernel<<<BB * LL, 256>>>(f, P);

    // ---- G4: wyT[l,c] = sum_m P[l,m] eta[c,m] + bw[c]  (2-pass) ----
    {
        dim3 grid(CC / GBN, LL / GBM, BB);
        gemm_split_kernel<2, 0, 0><<<grid, 256, SM_DYN>>>(
            P, nullptr, e_hi, e_lo, bw,
            wyT, nullptr, nullptr, LL, LL, LL, CC, sLL, sLC, sLC);
    }

    // ---- BN ----
    bn_partial_kernel<<<128, 256>>>(wyT, psum, psq);
    bn_final_kernel<<<1, 256>>>(psum, psq, mean, rstd);
    {
        dim3 g2(LL / 32, CC / 32, BB), b2(32, 8);
        bn_apply_kernel<<<g2, b2>>>(wyT, x, gamma, beta, mean, rstd, out);
    }
}

// round 7
// speedup vs baseline: 4.0371x; 1.1480x over previous
#include <cuda_runtime.h>
#include <cuda_fp16.h>
#include <math.h>
#include <stdint.h>

#define BB 16
#define CC 256
#define LL 2048
#define EPS 1e-5f

// ======================= helpers =======================
__device__ __forceinline__ uint32_t smem_to_u32(const void* p) {
    uint32_t a;
    asm("{ .reg .u64 t; cvta.to.shared.u64 t, %1; cvt.u32.u64 %0, t; }" : "=r"(a) : "l"(p));
    return a;
}
__device__ __forceinline__ void cp_async16(uint32_t s, const void* g) {
    asm volatile("cp.async.cg.shared.global [%0], [%1], 16;" :: "r"(s), "l"(g));
}
#define CP_COMMIT() asm volatile("cp.async.commit_group;" ::: "memory")
#define CP_WAIT(n)  asm volatile("cp.async.wait_group %0;" :: "n"(n) : "memory")

__device__ __forceinline__ void ldsm4(uint32_t* r, uint32_t a) {
    asm volatile("ldmatrix.sync.aligned.m8n8.x4.shared.b16 {%0,%1,%2,%3}, [%4];"
                 : "=r"(r[0]), "=r"(r[1]), "=r"(r[2]), "=r"(r[3]) : "r"(a));
}
__device__ __forceinline__ void mma16816(float* c, const uint32_t* a, uint32_t b0, uint32_t b1) {
    asm volatile("mma.sync.aligned.m16n8k16.row.col.f32.f16.f16.f32 "
                 "{%0,%1,%2,%3}, {%4,%5,%6,%7}, {%8,%9}, {%0,%1,%2,%3};"
                 : "+f"(c[0]), "+f"(c[1]), "+f"(c[2]), "+f"(c[3])
                 : "r"(a[0]), "r"(a[1]), "r"(a[2]), "r"(a[3]), "r"(b0), "r"(b1));
}
__device__ __forceinline__ uint32_t pack_h2(__half a, __half b) {
    __half2 t = __halves2half2(a, b);
    return *reinterpret_cast<uint32_t*>(&t);
}

// ======================= scratch =======================
#define NLC  ((size_t)BB * LL * CC)
#define NLLs ((size_t)BB * LL * LL)

__device__ __align__(256) __half d_xT_hi[NLC], d_xT_lo[NLC];       // x^T (B,L,C)
__device__ __align__(256) __half d_Mt_hi[CC * CC], d_Mt_lo[CC * CC]; // Wp^T Wt
__device__ __align__(256) __half d_Nt_hi[CC * CC], d_Nt_lo[CC * CC]; // Ww Wg
__device__ float d_qv[CC], d_rv[CC];                                // Wp^T bt ; Ww bg
__device__ __align__(256) __half d_kT_hi[NLC], d_kT_lo[NLC];       // kappa^T (B,L,C)
__device__ __align__(256) __half d_e_hi[NLC], d_e_lo[NLC];         // eta (B,C,L)
__device__ __align__(256) float  d_f[NLLs];                        // logits (B,L,L)
__device__ __align__(256) __half d_P[NLLs];                        // softmax fp16
__device__ __align__(256) float  d_wyT[NLC];                       // W_y^T (B,L,C)
__device__ float d_psum[128 * CC], d_psq[128 * CC];
__device__ float d_mean[CC], d_rstd[CC];

// ======================= prep kernels =======================
__global__ __launch_bounds__(256)
void transpose_split_kernel(const float* __restrict__ src,
                            __half* __restrict__ dhi, __half* __restrict__ dlo,
                            int R, int S)
{
    __shared__ float tile[32][33];
    const size_t bo = (size_t)R * S * blockIdx.z;
    const int s0 = blockIdx.x * 32, r0 = blockIdx.y * 32;
    const int tx = threadIdx.x, ty = threadIdx.y;
#pragma unroll
    for (int k = 0; k < 4; k++)
        tile[ty + 8 * k][tx] = src[bo + (size_t)(r0 + ty + 8 * k) * S + s0 + tx];
    __syncthreads();
#pragma unroll
    for (int k = 0; k < 4; k++) {
        float v = tile[tx][ty + 8 * k];
        __half h = __float2half(v);
        size_t di = bo + (size_t)(s0 + ty + 8 * k) * R + r0 + tx;
        dhi[di] = h;
        dlo[di] = __float2half(v - __half2float(h));
    }
}

// Weight products: blockIdx.y==0 -> Mt = Wp^T Wt, qv = Wp^T bt
//                  blockIdx.y==1 -> Nt = Ww Wg,   rv = Ww bg
__global__ __launch_bounds__(256)
void wprep_kernel(const float* __restrict__ Wt, const float* __restrict__ bt,
                  const float* __restrict__ Wp,
                  const float* __restrict__ Wg, const float* __restrict__ bg,
                  const float* __restrict__ Ww,
                  __half* __restrict__ Mhi, __half* __restrict__ Mlo, float* __restrict__ qv,
                  __half* __restrict__ Nhi, __half* __restrict__ Nlo, float* __restrict__ rv)
{
    const int c = blockIdx.x, k = threadIdx.x;
    if (blockIdx.y == 0) {
        float acc = 0.f;
        for (int j = 0; j < CC; j++) acc += Wp[j * CC + c] * Wt[j * CC + k];
        __half h = __float2half(acc);
        Mhi[c * CC + k] = h;
        Mlo[c * CC + k] = __float2half(acc - __half2float(h));
        if (k == 0) {
            float q = 0.f;
            for (int j = 0; j < CC; j++) q += Wp[j * CC + c] * bt[j];
            qv[c] = q;
        }
    } else {
        float acc = 0.f;
        for (int j = 0; j < CC; j++) acc += Ww[c * CC + j] * Wg[j * CC + k];
        __half h = __float2half(acc);
        Nhi[c * CC + k] = h;
        Nlo[c * CC + k] = __float2half(acc - __half2float(h));
        if (k == 0) {
            float r = 0.f;
            for (int j = 0; j < CC; j++) r += Ww[c * CC + j] * bg[j];
            rv[c] = r;
        }
    }
}

// ======================= split-fp16 mma.sync GEMM =======================
// D[m,n] = sum_k A(m,k)*B(n,k); K-major fp16 hi/lo; NPASS fp32-acc passes:
//   pass0 Ahi*Bhi, pass1 Ahi*Blo, pass2 Alo*Bhi
// Tile 128x128x64; 8 warps (2x4), m16n8k16; 3-stage cp.async pipeline,
// single barrier per chunk, register fragment double-buffering.
#define GBM 128
#define GBN 128
#define GBK 64
#define STAGE 32768
#define NSTAGE 3
#define SM_DYN (NSTAGE * STAGE)

template<int NPASS, int EPI, int BIASROW>
__global__ __launch_bounds__(256, 2)
void gemm_split_kernel(const __half* __restrict__ Ahi, const __half* __restrict__ Alo,
                       const __half* __restrict__ Bhi, const __half* __restrict__ Blo,
                       const float* __restrict__ bias,
                       float* __restrict__ Cf,
                       __half* __restrict__ Chi, __half* __restrict__ Clo,
                       int K, int lda, int ldb, int ldc,
                       size_t sA, size_t sB, size_t sC)
{
    extern __shared__ char smem[];
    const uint32_t sbase = smem_to_u32(smem);

    const int tid  = threadIdx.x;
    const int lane = tid & 31;
    const int wid  = tid >> 5;
    const int wm   = wid >> 2;
    const int wn   = wid & 3;

    const size_t aoff = (size_t)blockIdx.z * sA;
    const size_t boff = (size_t)blockIdx.z * sB;
    const int mBase = blockIdx.y * GBM;
    const int nBase = blockIdx.x * GBN;
    const int KC = K / GBK, NCH = NPASS * KC;

    float acc[4][4][4];
#pragma unroll
    for (int i = 0; i < 4; i++)
#pragma unroll
        for (int j = 0; j < 4; j++)
#pragma unroll
            for (int q = 0; q < 4; q++) acc[i][j][q] = 0.f;

    auto issue_chunk = [&](int ch) {
        const int s = ch % NSTAGE;
        const int pass = ch / KC;
        const int koff = (ch - pass * KC) * GBK;
        const __half* pa = ((pass < 2) ? Ahi : Alo) + aoff;
        const __half* pb = ((pass == 1) ? Blo : Bhi) + boff;
        const uint32_t Ab = sbase + s * STAGE;
        const uint32_t Bb = Ab + 16384;
#pragma unroll
        for (int i = 0; i < 4; i++) {
            int idx = tid + i * 256;
            int r = idx >> 3, c = idx & 7;
            uint32_t d = Ab + r * 128 + ((c ^ (r & 7)) << 4);
            cp_async16(d, pa + (size_t)(mBase + r) * lda + koff + c * 8);
        }
#pragma unroll
        for (int i = 0; i < 4; i++) {
            int idx = tid + i * 256;
            int r = idx >> 3, c = idx & 7;
            uint32_t d = Bb + r * 128 + ((c ^ (r & 7)) << 4);
            cp_async16(d, pb + (size_t)(nBase + r) * ldb + koff + c * 8);
        }
    };

    issue_chunk(0); CP_COMMIT();
    if (NCH > 1) issue_chunk(1);
    CP_COMMIT();

    const int laA = lane & 15;
    const int lcA = lane >> 4;
    const int lrB = ((lane >> 4) << 3) + (lane & 7);
    const int lcB = (lane >> 3) & 1;

    uint32_t afr[2][4][4], bfr[2][2][4];

    for (int ch = 0; ch < NCH; ch++) {
        CP_WAIT(1);                 // stage ch data arrived
        __syncthreads();            // all warps done reading stage ch-1

        const uint32_t Ab = sbase + (ch % NSTAGE) * STAGE;
        const uint32_t Bb = Ab + 16384;

        // load ks=0 fragments first -> ldsm latency overlaps cp.async issue
#pragma unroll
        for (int i = 0; i < 4; i++) {
            int row = wm * 64 + i * 16 + laA;
            ldsm4(afr[0][i], Ab + row * 128 + ((lcA ^ (row & 7)) << 4));
        }
#pragma unroll
        for (int j = 0; j < 2; j++) {
            int row = wn * 32 + j * 16 + lrB;
            ldsm4(bfr[0][j], Bb + row * 128 + ((lcB ^ (row & 7)) << 4));
        }

        if (ch + 2 < NCH) issue_chunk(ch + 2);
        CP_COMMIT();

#pragma unroll
        for (int ks = 0; ks < 4; ks++) {
            if (ks < 3) {
                const int nb = (ks + 1) & 1;
#pragma unroll
                for (int i = 0; i < 4; i++) {
                    int row = wm * 64 + i * 16 + laA;
                    int chk = (ks + 1) * 2 + lcA;
                    ldsm4(afr[nb][i], Ab + row * 128 + ((chk ^ (row & 7)) << 4));
                }
#pragma unroll
                for (int j = 0; j < 2; j++) {
                    int row = wn * 32 + j * 16 + lrB;
                    int chk = (ks + 1) * 2 + lcB;
                    ldsm4(bfr[nb][j], Bb + row * 128 + ((chk ^ (row & 7)) << 4));
                }
            }
            const int b = ks & 1;
#pragma unroll
            for (int i = 0; i < 4; i++)
#pragma unroll
                for (int j = 0; j < 4; j++)
                    mma16816(acc[i][j], afr[b][i], bfr[b][j >> 1][(j & 1) * 2],
                             bfr[b][j >> 1][(j & 1) * 2 + 1]);
        }
    }

    // ---- epilogue ----
    const int g  = lane >> 2;
    const int tg = lane & 3;
#pragma unroll
    for (int i = 0; i < 4; i++) {
        const int rm0 = mBase + wm * 64 + i * 16 + g;
        const int rm1 = rm0 + 8;
        float rb0 = 0.f, rb1 = 0.f;
        if (BIASROW && bias) { rb0 = bias[rm0]; rb1 = bias[rm1]; }
#pragma unroll
        for (int j = 0; j < 4; j++) {
            const int cn = nBase + wn * 32 + j * 8 + tg * 2;
            float c0 = acc[i][j][0], c1 = acc[i][j][1];
            float c2 = acc[i][j][2], c3 = acc[i][j][3];
            if (bias) {
                if (BIASROW) { c0 += rb0; c1 += rb0; c2 += rb1; c3 += rb1; }
                else {
                    float b0 = bias[cn], b1 = bias[cn + 1];
                    c0 += b0; c1 += b1; c2 += b0; c3 += b1;
                }
            }
            const size_t o0 = (size_t)blockIdx.z * sC + (size_t)rm0 * ldc + cn;
            const size_t o1 = (size_t)blockIdx.z * sC + (size_t)rm1 * ldc + cn;
            if (EPI == 0) {
                *(float2*)(Cf + o0) = make_float2(c0, c1);
                *(float2*)(Cf + o1) = make_float2(c2, c3);
            } else {
                __half h0 = __float2half(c0), h1 = __float2half(c1);
                __half h2 = __float2half(c2), h3 = __float2half(c3);
                __half l0 = __float2half(c0 - __half2float(h0));
                __half l1 = __float2half(c1 - __half2float(h1));
                __half l2 = __float2half(c2 - __half2float(h2));
                __half l3 = __float2half(c3 - __half2float(h3));
                *(uint32_t*)(Chi + o0) = pack_h2(h0, h1);
                *(uint32_t*)(Chi + o1) = pack_h2(h2, h3);
                *(uint32_t*)(Clo + o0) = pack_h2(l0, l1);
                *(uint32_t*)(Clo + o1) = pack_h2(l2, l3);
            }
        }
    }
}

// ======================= softmax: fp32 logits -> fp16 P =======================
__global__ __launch_bounds__(256)
void softmax_kernel(const float* __restrict__ f, __half* __restrict__ P)
{
    __shared__ float red[8];
    const size_t ro = (size_t)blockIdx.x * LL;
    const int tid = threadIdx.x;
    float v[8];
    float m = -INFINITY;
#pragma unroll
    for (int j = 0; j < 8; j++) {
        v[j] = f[ro + tid + j * 256];
        m = fmaxf(m, v[j]);
    }
#pragma unroll
    for (int o = 16; o; o >>= 1) m = fmaxf(m, __shfl_xor_sync(0xffffffffu, m, o));
    if ((tid & 31) == 0) red[tid >> 5] = m;
    __syncthreads();
    float bm = red[0];
#pragma unroll
    for (int w = 1; w < 8; w++) bm = fmaxf(bm, red[w]);
    float s = 0.f;
#pragma unroll
    for (int j = 0; j < 8; j++) { v[j] = __expf(v[j] - bm); s += v[j]; }
#pragma unroll
    for (int o = 16; o; o >>= 1) s += __shfl_xor_sync(0xffffffffu, s, o);
    __syncthreads();
    if ((tid & 31) == 0) red[tid >> 5] = s;
    __syncthreads();
    float bs = 0.f;
#pragma unroll
    for (int w = 0; w < 8; w++) bs += red[w];
    const float inv = 1.f / bs;
#pragma unroll
    for (int j = 0; j < 8; j++)
        P[ro + tid + j * 256] = __float2half(v[j] * inv);
}

// ======================= BatchNorm =======================
__global__ __launch_bounds__(256)
void bn_partial_kernel(const float* __restrict__ wyT, float* __restrict__ psum, float* __restrict__ psq)
{
    const int c = threadIdx.x;
    float s = 0.f, q = 0.f;
    const size_t r0 = (size_t)blockIdx.x * 256;
    for (int r = 0; r < 256; r++) {
        float v = wyT[(r0 + r) * CC + c];
        s += v; q += v * v;
    }
    psum[blockIdx.x * CC + c] = s;
    psq [blockIdx.x * CC + c] = q;
}

__global__ __launch_bounds__(256)
void bn_final_kernel(const float* __restrict__ psum, const float* __restrict__ psq,
                     float* __restrict__ mean, float* __restrict__ rstd)
{
    const int c = threadIdx.x;
    float s = 0.f, q = 0.f;
    for (int i = 0; i < 128; i++) { s += psum[i * CC + c]; q += psq[i * CC + c]; }
    const float inv_n = 1.f / (float)(BB * LL);
    float mu = s * inv_n;
    mean[c] = mu;
    rstd[c] = rsqrtf(q * inv_n - mu * mu + EPS);
}

__global__ __launch_bounds__(256)
void bn_apply_kernel(const float* __restrict__ wyT, const float* __restrict__ x,
                     const float* __restrict__ gamma, const float* __restrict__ beta,
                     const float* __restrict__ mean, const float* __restrict__ rstd,
                     float* __restrict__ out)
{
    __shared__ float tile[32][33];
    const int l0 = blockIdx.x * 32, c0 = blockIdx.y * 32;
    const size_t bo = (size_t)blockIdx.z * CC * LL;
    const int tx = threadIdx.x, ty = threadIdx.y;
#pragma unroll
    for (int k = 0; k < 4; k++)
        tile[ty + 8 * k][tx] = wyT[bo + (size_t)(l0 + ty + 8 * k) * CC + c0 + tx];
    __syncthreads();
#pragma unroll
    for (int k = 0; k < 4; k++) {
        const int c = c0 + ty + 8 * k, l = l0 + tx;
        float v = tile[tx][ty + 8 * k];
        size_t oi = bo + (size_t)c * LL + l;
        out[oi] = gamma[c] * (v - mean[c]) * rstd[c] + beta[c] + x[oi];
    }
}

// ======================= launch =======================
extern "C" void kernel_launch(void* const* d_in, const int* in_sizes, int n_in,
                              void* d_out, int out_size)
{
    const float* x     = (const float*)d_in[0];
    const float* Wg    = (const float*)d_in[1];
    const float* bg    = (const float*)d_in[2];
    const float* Wt    = (const float*)d_in[3];
    const float* bt    = (const float*)d_in[4];
    const float* Wp    = (const float*)d_in[5];
    const float* bp    = (const float*)d_in[6];   // unused: row-constant under softmax
    const float* Ww    = (const float*)d_in[7];
    const float* bw    = (const float*)d_in[8];
    const float* gamma = (const float*)d_in[9];
    const float* beta  = (const float*)d_in[10];
    float* out = (float*)d_out;
    (void)bp;

    __half *xT_hi, *xT_lo, *Mt_hi, *Mt_lo, *Nt_hi, *Nt_lo, *kT_hi, *kT_lo, *e_hi, *e_lo, *P;
    float *qv, *rv, *f, *wyT, *psum, *psq, *mean, *rstd;
    cudaGetSymbolAddress((void**)&xT_hi, d_xT_hi);
    cudaGetSymbolAddress((void**)&xT_lo, d_xT_lo);
    cudaGetSymbolAddress((void**)&Mt_hi, d_Mt_hi);
    cudaGetSymbolAddress((void**)&Mt_lo, d_Mt_lo);
    cudaGetSymbolAddress((void**)&Nt_hi, d_Nt_hi);
    cudaGetSymbolAddress((void**)&Nt_lo, d_Nt_lo);
    cudaGetSymbolAddress((void**)&qv,    d_qv);
    cudaGetSymbolAddress((void**)&rv,    d_rv);
    cudaGetSymbolAddress((void**)&kT_hi, d_kT_hi);
    cudaGetSymbolAddress((void**)&kT_lo, d_kT_lo);
    cudaGetSymbolAddress((void**)&e_hi,  d_e_hi);
    cudaGetSymbolAddress((void**)&e_lo,  d_e_lo);
    cudaGetSymbolAddress((void**)&f,     d_f);
    cudaGetSymbolAddress((void**)&P,     d_P);
    cudaGetSymbolAddress((void**)&wyT,   d_wyT);
    cudaGetSymbolAddress((void**)&psum,  d_psum);
    cudaGetSymbolAddress((void**)&psq,   d_psq);
    cudaGetSymbolAddress((void**)&mean,  d_mean);
    cudaGetSymbolAddress((void**)&rstd,  d_rstd);

    cudaFuncSetAttribute(gemm_split_kernel<3, 0, 0>, cudaFuncAttributeMaxDynamicSharedMemorySize, SM_DYN);
    cudaFuncSetAttribute(gemm_split_kernel<3, 1, 0>, cudaFuncAttributeMaxDynamicSharedMemorySize, SM_DYN);
    cudaFuncSetAttribute(gemm_split_kernel<3, 1, 1>, cudaFuncAttributeMaxDynamicSharedMemorySize, SM_DYN);
    cudaFuncSetAttribute(gemm_split_kernel<1, 0, 0>, cudaFuncAttributeMaxDynamicSharedMemorySize, SM_DYN);

    const size_t sLC = (size_t)LL * CC;
    const size_t sLL = (size_t)LL * LL;

    // ---- prep: xT split; folded weight products ----
    {
        dim3 g1(LL / 32, CC / 32, BB), b1(32, 8);
        transpose_split_kernel<<<g1, b1>>>(x, xT_hi, xT_lo, CC, LL);
        dim3 gw(CC, 2);
        wprep_kernel<<<gw, CC>>>(Wt, bt, Wp, Wg, bg, Ww,
                                 Mt_hi, Mt_lo, qv, Nt_hi, Nt_lo, rv);
    }

    // ---- G1: kappaT[l,c] = sum_k xT[l,k] Mt[c,k] + qv[c]   (B,L,C) ----
    {
        dim3 grid(CC / GBN, LL / GBM, BB);
        gemm_split_kernel<3, 1, 0><<<grid, 256, SM_DYN>>>(
            xT_hi, xT_lo, Mt_hi, Mt_lo, qv,
            nullptr, kT_hi, kT_lo, CC, CC, CC, CC, sLC, 0, sLC);
    }
    // ---- G2: eta[c,l] = sum_k Nt[c,k] xT[l,k] + rv[c]   (B,C,L) ----
    {
        dim3 grid(LL / GBN, CC / GBM, BB);
        gemm_split_kernel<3, 1, 1><<<grid, 256, SM_DYN>>>(
            Nt_hi, Nt_lo, xT_hi, xT_lo, rv,
            nullptr, e_hi, e_lo, CC, CC, CC, LL, 0, sLC, sLC);
    }
    // ---- G3: f[l,m] = sum_c kappaT[l,c] xT[m,c]  (logits up to row-const) ----
    {
        dim3 grid(LL / GBN, LL / GBM, BB);
        gemm_split_kernel<3, 0, 0><<<grid, 256, SM_DYN>>>(
            kT_hi, kT_lo, xT_hi, xT_lo, nullptr,
            f, nullptr, nullptr, CC, CC, CC, LL, sLC, sLC, sLL);
    }
    // ---- softmax -> P fp16 ----
    softmax_kernel<<<BB * LL, 256>>>(f, P);

    // ---- G4: wyT[l,c] = sum_m P[l,m] eta_hi[c,m] + bw[c]  (1-pass) ----
    {
        dim3 grid(CC / GBN, LL / GBM, BB);
        gemm_split_kernel<1, 0, 0><<<grid, 256, SM_DYN>>>(
            P, nullptr, e_hi, nullptr, bw,
            wyT, nullptr, nullptr, LL, LL, LL, CC, sLL, sLC, sLC);
    }

    // ---- BN ----
    bn_partial_kernel<<<128, 256>>>(wyT, psum, psq);
    bn_final_kernel<<<1, 256>>>(psum, psq, mean, rstd);
    {
        dim3 g2(LL / 32, CC / 32, BB), b2(32, 8);
        bn_apply_kernel<<<g2, b2>>>(wyT, x, gamma, beta, mean, rstd, out);
    }
}

// round 8
// speedup vs baseline: 4.5300x; 1.1221x over previous
#include <cuda_runtime.h>
#include <cuda_fp16.h>
#include <math.h>
#include <stdint.h>

#define BB 16
#define CC 256
#define LL 2048
#define EPS 1e-5f

// ======================= helpers =======================
__device__ __forceinline__ uint32_t smem_to_u32(const void* p) {
    uint32_t a;
    asm("{ .reg .u64 t; cvta.to.shared.u64 t, %1; cvt.u32.u64 %0, t; }" : "=r"(a) : "l"(p));
    return a;
}
__device__ __forceinline__ void cp_async16(uint32_t s, const void* g) {
    asm volatile("cp.async.cg.shared.global [%0], [%1], 16;" :: "r"(s), "l"(g));
}
#define CP_COMMIT() asm volatile("cp.async.commit_group;" ::: "memory")
#define CP_WAIT(n)  asm volatile("cp.async.wait_group %0;" :: "n"(n) : "memory")

__device__ __forceinline__ void ldsm4(uint32_t* r, uint32_t a) {
    asm volatile("ldmatrix.sync.aligned.m8n8.x4.shared.b16 {%0,%1,%2,%3}, [%4];"
                 : "=r"(r[0]), "=r"(r[1]), "=r"(r[2]), "=r"(r[3]) : "r"(a));
}
__device__ __forceinline__ void mma16816(float* c, const uint32_t* a, uint32_t b0, uint32_t b1) {
    asm volatile("mma.sync.aligned.m16n8k16.row.col.f32.f16.f16.f32 "
                 "{%0,%1,%2,%3}, {%4,%5,%6,%7}, {%8,%9}, {%0,%1,%2,%3};"
                 : "+f"(c[0]), "+f"(c[1]), "+f"(c[2]), "+f"(c[3])
                 : "r"(a[0]), "r"(a[1]), "r"(a[2]), "r"(a[3]), "r"(b0), "r"(b1));
}
__device__ __forceinline__ uint32_t pack_h2(__half a, __half b) {
    __half2 t = __halves2half2(a, b);
    return *reinterpret_cast<uint32_t*>(&t);
}

// ======================= scratch =======================
#define NLC  ((size_t)BB * LL * CC)
#define NLLs ((size_t)BB * LL * LL)

__device__ __align__(256) __half d_xT_hi[NLC], d_xT_lo[NLC];       // x^T (B,L,C)
__device__ __align__(256) __half d_Mt_hi[CC * CC], d_Mt_lo[CC * CC]; // Wp^T Wt
__device__ __align__(256) __half d_Nt_hi[CC * CC], d_Nt_lo[CC * CC]; // Ww Wg
__device__ float d_qv[CC], d_rv[CC];                                // Wp^T bt ; Ww bg
__device__ __align__(256) __half d_kT_hi[NLC], d_kT_lo[NLC];       // kappa^T (B,L,C)
__device__ __align__(256) __half d_e_hi[NLC], d_e_lo[NLC];         // eta (B,C,L)
__device__ __align__(256) float  d_f[NLLs];                        // logits (B,L,L)
__device__ __align__(256) __half d_P[NLLs];                        // softmax fp16
__device__ __align__(256) float  d_wyT[NLC];                       // W_y^T (B,L,C)
__device__ float d_psum[128 * CC], d_psq[128 * CC];
__device__ float d_mean[CC], d_rstd[CC];

// ======================= prep kernels =======================
__global__ __launch_bounds__(256)
void transpose_split_kernel(const float* __restrict__ src,
                            __half* __restrict__ dhi, __half* __restrict__ dlo,
                            int R, int S)
{
    __shared__ float tile[32][33];
    const size_t bo = (size_t)R * S * blockIdx.z;
    const int s0 = blockIdx.x * 32, r0 = blockIdx.y * 32;
    const int tx = threadIdx.x, ty = threadIdx.y;
#pragma unroll
    for (int k = 0; k < 4; k++)
        tile[ty + 8 * k][tx] = src[bo + (size_t)(r0 + ty + 8 * k) * S + s0 + tx];
    __syncthreads();
#pragma unroll
    for (int k = 0; k < 4; k++) {
        float v = tile[tx][ty + 8 * k];
        __half h = __float2half(v);
        size_t di = bo + (size_t)(s0 + ty + 8 * k) * R + r0 + tx;
        dhi[di] = h;
        dlo[di] = __float2half(v - __half2float(h));
    }
}

// Weight products: blockIdx.y==0 -> Mt = Wp^T Wt, qv = Wp^T bt
//                  blockIdx.y==1 -> Nt = Ww Wg,   rv = Ww bg
__global__ __launch_bounds__(256)
void wprep_kernel(const float* __restrict__ Wt, const float* __restrict__ bt,
                  const float* __restrict__ Wp,
                  const float* __restrict__ Wg, const float* __restrict__ bg,
                  const float* __restrict__ Ww,
                  __half* __restrict__ Mhi, __half* __restrict__ Mlo, float* __restrict__ qv,
                  __half* __restrict__ Nhi, __half* __restrict__ Nlo, float* __restrict__ rv)
{
    const int c = blockIdx.x, k = threadIdx.x;
    if (blockIdx.y == 0) {
        float acc = 0.f;
        for (int j = 0; j < CC; j++) acc += Wp[j * CC + c] * Wt[j * CC + k];
        __half h = __float2half(acc);
        Mhi[c * CC + k] = h;
        Mlo[c * CC + k] = __float2half(acc - __half2float(h));
        if (k == 0) {
            float q = 0.f;
            for (int j = 0; j < CC; j++) q += Wp[j * CC + c] * bt[j];
            qv[c] = q;
        }
    } else {
        float acc = 0.f;
        for (int j = 0; j < CC; j++) acc += Ww[c * CC + j] * Wg[j * CC + k];
        __half h = __float2half(acc);
        Nhi[c * CC + k] = h;
        Nlo[c * CC + k] = __float2half(acc - __half2float(h));
        if (k == 0) {
            float r = 0.f;
            for (int j = 0; j < CC; j++) r += Ww[c * CC + j] * bg[j];
            rv[c] = r;
        }
    }
}

// ======================= merged split-fp16 mma.sync GEMM =======================
// D[m,n] = sum_k A(m,k)*B(n,k); K-major fp16 hi/lo.
// MODE 1 (3-term split): KC "hi" chunks stage {Ahi,Bhi,Blo} and accumulate
//   Ahi*Bhi + Ahi*Blo (A fragments reused in regs), then KC "lo" chunks stage
//   {Alo,Bhi} and accumulate Alo*Bhi.
// MODE 0 (plain): KC chunks, Ahi*Bhi only.
// Tile 128x128x64; 8 warps (2x4), m16n8k16; 2-stage cp.async pipeline.
#define GBM 128
#define GBN 128
#define GBK 64

template<int MODE, int EPI, int BIASROW>
__global__ __launch_bounds__(256, 2)
void gemm_split_kernel(const __half* __restrict__ Ahi, const __half* __restrict__ Alo,
                       const __half* __restrict__ Bhi, const __half* __restrict__ Blo,
                       const float* __restrict__ bias,
                       float* __restrict__ Cf,
                       __half* __restrict__ Chi, __half* __restrict__ Clo,
                       int K, int lda, int ldb, int ldc,
                       size_t sA, size_t sB, size_t sC)
{
    constexpr uint32_t STG = MODE ? 49152u : 32768u;   // per-stage bytes
    extern __shared__ char smem[];
    const uint32_t sbase = smem_to_u32(smem);

    const int tid  = threadIdx.x;
    const int lane = tid & 31;
    const int wid  = tid >> 5;
    const int wm   = wid >> 2;
    const int wn   = wid & 3;

    const size_t aoff = (size_t)blockIdx.z * sA;
    const size_t boff = (size_t)blockIdx.z * sB;
    const int mBase = blockIdx.y * GBM;
    const int nBase = blockIdx.x * GBN;
    const int KC = K / GBK;
    const int NCH = MODE ? 2 * KC : KC;

    float acc[4][4][4];
#pragma unroll
    for (int i = 0; i < 4; i++)
#pragma unroll
        for (int j = 0; j < 4; j++)
#pragma unroll
            for (int q = 0; q < 4; q++) acc[i][j][q] = 0.f;

    auto issue_chunk = [&](int ch) {
        const bool hi = (ch < KC);
        const int koff = (hi ? ch : ch - KC) * GBK;
        const __half* pa = (hi ? Ahi : Alo) + aoff;
        const uint32_t Ab = sbase + (uint32_t)(ch & 1) * STG;
        const uint32_t B0 = Ab + 16384;
#pragma unroll
        for (int i = 0; i < 4; i++) {
            int idx = tid + i * 256;
            int r = idx >> 3, c = idx & 7;
            uint32_t d = Ab + r * 128 + ((c ^ (r & 7)) << 4);
            cp_async16(d, pa + (size_t)(mBase + r) * lda + koff + c * 8);
        }
#pragma unroll
        for (int i = 0; i < 4; i++) {
            int idx = tid + i * 256;
            int r = idx >> 3, c = idx & 7;
            uint32_t d = B0 + r * 128 + ((c ^ (r & 7)) << 4);
            cp_async16(d, Bhi + boff + (size_t)(nBase + r) * ldb + koff + c * 8);
        }
        if (MODE && hi) {
            const uint32_t B1 = Ab + 32768;
#pragma unroll
            for (int i = 0; i < 4; i++) {
                int idx = tid + i * 256;
                int r = idx >> 3, c = idx & 7;
                uint32_t d = B1 + r * 128 + ((c ^ (r & 7)) << 4);
                cp_async16(d, Blo + boff + (size_t)(nBase + r) * ldb + koff + c * 8);
            }
        }
    };

    issue_chunk(0); CP_COMMIT();

    const int laA = lane & 15;
    const int lcA = lane >> 4;
    const int lrB = ((lane >> 4) << 3) + (lane & 7);
    const int lcB = (lane >> 3) & 1;

    for (int ch = 0; ch < NCH; ch++) {
        CP_WAIT(0);                 // chunk ch fully staged
        __syncthreads();            // all warps done reading stage (ch-1)&1
        if (ch + 1 < NCH) { issue_chunk(ch + 1); CP_COMMIT(); }

        const bool two = MODE && (ch < KC);
        const uint32_t Ab = sbase + (uint32_t)(ch & 1) * STG;
        const uint32_t B0 = Ab + 16384;
        const uint32_t B1 = Ab + 32768;

#pragma unroll
        for (int ks = 0; ks < 4; ks++) {
            uint32_t afr[4][4], bh[2][4], bl[2][4];
#pragma unroll
            for (int i = 0; i < 4; i++) {
                int row = wm * 64 + i * 16 + laA;
                int chk = ks * 2 + lcA;
                ldsm4(afr[i], Ab + row * 128 + ((chk ^ (row & 7)) << 4));
            }
#pragma unroll
            for (int j = 0; j < 2; j++) {
                int row = wn * 32 + j * 16 + lrB;
                int chk = ks * 2 + lcB;
                ldsm4(bh[j], B0 + row * 128 + ((chk ^ (row & 7)) << 4));
            }
            if (two) {
#pragma unroll
                for (int j = 0; j < 2; j++) {
                    int row = wn * 32 + j * 16 + lrB;
                    int chk = ks * 2 + lcB;
                    ldsm4(bl[j], B1 + row * 128 + ((chk ^ (row & 7)) << 4));
                }
            }
#pragma unroll
            for (int i = 0; i < 4; i++)
#pragma unroll
                for (int j = 0; j < 4; j++)
                    mma16816(acc[i][j], afr[i], bh[j >> 1][(j & 1) * 2],
                             bh[j >> 1][(j & 1) * 2 + 1]);
            if (two) {
#pragma unroll
                for (int i = 0; i < 4; i++)
#pragma unroll
                    for (int j = 0; j < 4; j++)
                        mma16816(acc[i][j], afr[i], bl[j >> 1][(j & 1) * 2],
                                 bl[j >> 1][(j & 1) * 2 + 1]);
            }
        }
    }

    // ---- epilogue ----
    const int g  = lane >> 2;
    const int tg = lane & 3;
#pragma unroll
    for (int i = 0; i < 4; i++) {
        const int rm0 = mBase + wm * 64 + i * 16 + g;
        const int rm1 = rm0 + 8;
        float rb0 = 0.f, rb1 = 0.f;
        if (BIASROW && bias) { rb0 = bias[rm0]; rb1 = bias[rm1]; }
#pragma unroll
        for (int j = 0; j < 4; j++) {
            const int cn = nBase + wn * 32 + j * 8 + tg * 2;
            float c0 = acc[i][j][0], c1 = acc[i][j][1];
            float c2 = acc[i][j][2], c3 = acc[i][j][3];
            if (bias) {
                if (BIASROW) { c0 += rb0; c1 += rb0; c2 += rb1; c3 += rb1; }
                else {
                    float b0 = bias[cn], b1 = bias[cn + 1];
                    c0 += b0; c1 += b1; c2 += b0; c3 += b1;
                }
            }
            const size_t o0 = (size_t)blockIdx.z * sC + (size_t)rm0 * ldc + cn;
            const size_t o1 = (size_t)blockIdx.z * sC + (size_t)rm1 * ldc + cn;
            if (EPI == 0) {
                *(float2*)(Cf + o0) = make_float2(c0, c1);
                *(float2*)(Cf + o1) = make_float2(c2, c3);
            } else {
                __half h0 = __float2half(c0), h1 = __float2half(c1);
                __half h2 = __float2half(c2), h3 = __float2half(c3);
                __half l0 = __float2half(c0 - __half2float(h0));
                __half l1 = __float2half(c1 - __half2float(h1));
                __half l2 = __float2half(c2 - __half2float(h2));
                __half l3 = __float2half(c3 - __half2float(h3));
                *(uint32_t*)(Chi + o0) = pack_h2(h0, h1);
                *(uint32_t*)(Chi + o1) = pack_h2(h2, h3);
                *(uint32_t*)(Clo + o0) = pack_h2(l0, l1);
                *(uint32_t*)(Clo + o1) = pack_h2(l2, l3);
            }
        }
    }
}

// ======================= softmax: fp32 logits -> fp16 P =======================
__global__ __launch_bounds__(256)
void softmax_kernel(const float* __restrict__ f, __half* __restrict__ P)
{
    __shared__ float red[8];
    const size_t ro = (size_t)blockIdx.x * LL;
    const int tid = threadIdx.x;
    float v[8];
    float m = -INFINITY;
#pragma unroll
    for (int j = 0; j < 8; j++) {
        v[j] = f[ro + tid + j * 256];
        m = fmaxf(m, v[j]);
    }
#pragma unroll
    for (int o = 16; o; o >>= 1) m = fmaxf(m, __shfl_xor_sync(0xffffffffu, m, o));
    if ((tid & 31) == 0) red[tid >> 5] = m;
    __syncthreads();
    float bm = red[0];
#pragma unroll
    for (int w = 1; w < 8; w++) bm = fmaxf(bm, red[w]);
    float s = 0.f;
#pragma unroll
    for (int j = 0; j < 8; j++) { v[j] = __expf(v[j] - bm); s += v[j]; }
#pragma unroll
    for (int o = 16; o; o >>= 1) s += __shfl_xor_sync(0xffffffffu, s, o);
    __syncthreads();
    if ((tid & 31) == 0) red[tid >> 5] = s;
    __syncthreads();
    float bs = 0.f;
#pragma unroll
    for (int w = 0; w < 8; w++) bs += red[w];
    const float inv = 1.f / bs;
#pragma unroll
    for (int j = 0; j < 8; j++)
        P[ro + tid + j * 256] = __float2half(v[j] * inv);
}

// ======================= BatchNorm =======================
__global__ __launch_bounds__(256)
void bn_partial_kernel(const float* __restrict__ wyT, float* __restrict__ psum, float* __restrict__ psq)
{
    const int c = threadIdx.x;
    float s = 0.f, q = 0.f;
    const size_t r0 = (size_t)blockIdx.x * 256;
    for (int r = 0; r < 256; r++) {
        float v = wyT[(r0 + r) * CC + c];
        s += v; q += v * v;
    }
    psum[blockIdx.x * CC + c] = s;
    psq [blockIdx.x * CC + c] = q;
}

__global__ __launch_bounds__(256)
void bn_final_kernel(const float* __restrict__ psum, const float* __restrict__ psq,
                     float* __restrict__ mean, float* __restrict__ rstd)
{
    const int c = threadIdx.x;
    float s = 0.f, q = 0.f;
    for (int i = 0; i < 128; i++) { s += psum[i * CC + c]; q += psq[i * CC + c]; }
    const float inv_n = 1.f / (float)(BB * LL);
    float mu = s * inv_n;
    mean[c] = mu;
    rstd[c] = rsqrtf(q * inv_n - mu * mu + EPS);
}

__global__ __launch_bounds__(256)
void bn_apply_kernel(const float* __restrict__ wyT, const float* __restrict__ x,
                     const float* __restrict__ gamma, const float* __restrict__ beta,
                     const float* __restrict__ mean, const float* __restrict__ rstd,
                     float* __restrict__ out)
{
    __shared__ float tile[32][33];
    const int l0 = blockIdx.x * 32, c0 = blockIdx.y * 32;
    const size_t bo = (size_t)blockIdx.z * CC * LL;
    const int tx = threadIdx.x, ty = threadIdx.y;
#pragma unroll
    for (int k = 0; k < 4; k++)
        tile[ty + 8 * k][tx] = wyT[bo + (size_t)(l0 + ty + 8 * k) * CC + c0 + tx];
    __syncthreads();
#pragma unroll
    for (int k = 0; k < 4; k++) {
        const int c = c0 + ty + 8 * k, l = l0 + tx;
        float v = tile[tx][ty + 8 * k];
        size_t oi = bo + (size_t)c * LL + l;
        out[oi] = gamma[c] * (v - mean[c]) * rstd[c] + beta[c] + x[oi];
    }
}

// ======================= launch =======================
extern "C" void kernel_launch(void* const* d_in, const int* in_sizes, int n_in,
                              void* d_out, int out_size)
{
    const float* x     = (const float*)d_in[0];
    const float* Wg    = (const float*)d_in[1];
    const float* bg    = (const float*)d_in[2];
    const float* Wt    = (const float*)d_in[3];
    const float* bt    = (const float*)d_in[4];
    const float* Wp    = (const float*)d_in[5];
    const float* bp    = (const float*)d_in[6];   // unused: row-constant under softmax
    const float* Ww    = (const float*)d_in[7];
    const float* bw    = (const float*)d_in[8];
    const float* gamma = (const float*)d_in[9];
    const float* beta  = (const float*)d_in[10];
    float* out = (float*)d_out;
    (void)bp;

    __half *xT_hi, *xT_lo, *Mt_hi, *Mt_lo, *Nt_hi, *Nt_lo, *kT_hi, *kT_lo, *e_hi, *e_lo, *P;
    float *qv, *rv, *f, *wyT, *psum, *psq, *mean, *rstd;
    cudaGetSymbolAddress((void**)&xT_hi, d_xT_hi);
    cudaGetSymbolAddress((void**)&xT_lo, d_xT_lo);
    cudaGetSymbolAddress((void**)&Mt_hi, d_Mt_hi);
    cudaGetSymbolAddress((void**)&Mt_lo, d_Mt_lo);
    cudaGetSymbolAddress((void**)&Nt_hi, d_Nt_hi);
    cudaGetSymbolAddress((void**)&Nt_lo, d_Nt_lo);
    cudaGetSymbolAddress((void**)&qv,    d_qv);
    cudaGetSymbolAddress((void**)&rv,    d_rv);
    cudaGetSymbolAddress((void**)&kT_hi, d_kT_hi);
    cudaGetSymbolAddress((void**)&kT_lo, d_kT_lo);
    cudaGetSymbolAddress((void**)&e_hi,  d_e_hi);
    cudaGetSymbolAddress((void**)&e_lo,  d_e_lo);
    cudaGetSymbolAddress((void**)&f,     d_f);
    cudaGetSymbolAddress((void**)&P,     d_P);
    cudaGetSymbolAddress((void**)&wyT,   d_wyT);
    cudaGetSymbolAddress((void**)&psum,  d_psum);
    cudaGetSymbolAddress((void**)&psq,   d_psq);
    cudaGetSymbolAddress((void**)&mean,  d_mean);
    cudaGetSymbolAddress((void**)&rstd,  d_rstd);

    const int SM1 = 2 * 49152;   // MODE 1
    const int SM0 = 2 * 32768;   // MODE 0
    cudaFuncSetAttribute(gemm_split_kernel<1, 0, 0>, cudaFuncAttributeMaxDynamicSharedMemorySize, SM1);
    cudaFuncSetAttribute(gemm_split_kernel<1, 1, 0>, cudaFuncAttributeMaxDynamicSharedMemorySize, SM1);
    cudaFuncSetAttribute(gemm_split_kernel<1, 1, 1>, cudaFuncAttributeMaxDynamicSharedMemorySize, SM1);
    cudaFuncSetAttribute(gemm_split_kernel<0, 0, 0>, cudaFuncAttributeMaxDynamicSharedMemorySize, SM0);

    const size_t sLC = (size_t)LL * CC;
    const size_t sLL = (size_t)LL * LL;

    // ---- prep: xT split; folded weight products ----
    {
        dim3 g1(LL / 32, CC / 32, BB), b1(32, 8);
        transpose_split_kernel<<<g1, b1>>>(x, xT_hi, xT_lo, CC, LL);
        dim3 gw(CC, 2);
        wprep_kernel<<<gw, CC>>>(Wt, bt, Wp, Wg, bg, Ww,
                                 Mt_hi, Mt_lo, qv, Nt_hi, Nt_lo, rv);
    }

    // ---- G1: kappaT[l,c] = sum_k xT[l,k] Mt[c,k] + qv[c]   (B,L,C) ----
    {
        dim3 grid(CC / GBN, LL / GBM, BB);
        gemm_split_kernel<1, 1, 0><<<grid, 256, SM1>>>(
            xT_hi, xT_lo, Mt_hi, Mt_lo, qv,
            nullptr, kT_hi, kT_lo, CC, CC, CC, CC, sLC, 0, sLC);
    }
    // ---- G2: eta[c,l] = sum_k Nt[c,k] xT[l,k] + rv[c]   (B,C,L) ----
    {
        dim3 grid(LL / GBN, CC / GBM, BB);
        gemm_split_kernel<1, 1, 1><<<grid, 256, SM1>>>(
            Nt_hi, Nt_lo, xT_hi, xT_lo, rv,
            nullptr, e_hi, e_lo, CC, CC, CC, LL, 0, sLC, sLC);
    }
    // ---- G3: f[l,m] = sum_c kappaT[l,c] xT[m,c]  (logits up to row-const) ----
    {
        dim3 grid(LL / GBN, LL / GBM, BB);
        gemm_split_kernel<1, 0, 0><<<grid, 256, SM1>>>(
            kT_hi, kT_lo, xT_hi, xT_lo, nullptr,
            f, nullptr, nullptr, CC, CC, CC, LL, sLC, sLC, sLL);
    }
    // ---- softmax -> P fp16 ----
    softmax_kernel<<<BB * LL, 256>>>(f, P);

    // ---- G4: wyT[l,c] = sum_m P[l,m] eta_hi[c,m] + bw[c]  (1-pass) ----
    {
        dim3 grid(CC / GBN, LL / GBM, BB);
        gemm_split_kernel<0, 0, 0><<<grid, 256, SM0>>>(
            P, nullptr, e_hi, nullptr, bw,
            wyT, nullptr, nullptr, LL, LL, LL, CC, sLL, sLC, sLC);
    }

    // ---- BN ----
    bn_partial_kernel<<<128, 256>>>(wyT, psum, psq);
    bn_final_kernel<<<1, 256>>>(psum, psq, mean, rstd);
    {
        dim3 g2(LL / 32, CC / 32, BB), b2(32, 8);
        bn_apply_kernel<<<g2, b2>>>(wyT, x, gamma, beta, mean, rstd, out);
    }
}